// round 10
// baseline (speedup 1.0000x reference)
#include <cuda_runtime.h>
#include <cstdint>
#include <cstddef>

#define Bq   8
#define Cc   256
#define Hh   64
#define Ww   64
#define HWc  4096
#define TOTAL (8UL*256*4096)

// ---------------- scratch (device globals) ------------------------------------
__device__ float g_fe  [TOTAL];
__device__ float g_agg [TOTAL];
__device__ float g_enh [TOTAL];
__device__ float g_w1p [256*256];      // fragment-ready folded embed weight
__device__ float g_w2p [256*512];      // fragment-ready folded enhance weight
__device__ float g_b1f [256];
__device__ float g_b2f [256];
__device__ float g_nrm [Bq*HWc];
__device__ float g_dotp[4*Bq*9*HWc];   // partial dots [split][b][9][hw]
__device__ float g_simw[Bq*9*HWc];     // softmax weights [b][9][hw]
__device__ float g_poolp[Bq*32*256];
__device__ float g_pool[Bq*512];
__device__ float g_gate[Bq*256];

// ---------------- BN fold -> fragment-ready permuted layout --------------------
__global__ void fold_kernel(const float* __restrict__ w, const float* __restrict__ bsrc,
                            const float* __restrict__ gm, const float* __restrict__ bt,
                            const float* __restrict__ mn, const float* __restrict__ vr,
                            int cin, int which) {
    int o = blockIdx.x;
    float inv = gm[o] * rsqrtf(vr[o] + 1e-5f);
    float* wp = which ? g_w2p : g_w1p;
    float* bf = which ? g_b2f : g_b1f;
    const int tile = o >> 4;
    const int r = o & 15;
    const int gqv = r & 7;
    const int hi = r >> 3;
    for (int k = threadIdx.x; k < cin; k += blockDim.x) {
        int ci = k >> 4, kk = k & 15;
        int k8 = kk >> 3, kw = kk & 7;
        int lane = gqv * 4 + (kw & 3);
        int e = hi + ((kw >> 2) << 1);
        wp[(size_t)ci * 4096 + tile * 256 + k8 * 128 + lane * 4 + e] = inv * w[o * cin + k];
    }
    if (threadIdx.x == 0)
        bf[o] = bsrc[o] * inv + bt[o] - mn[o] * inv;
}

// ---------------- mma.sync tf32 GEMM (frag-ready A + merged k8 batch) ----------
#define BK   16
#define PADB 136
#define NSTG 4
#define ABUF 4096
#define BBUF (BK * PADB)
#define GSMEM (NSTG * (ABUF + BBUF) * 4)   // 100352 B

__device__ __forceinline__ void mma_tf32(float c[4], const uint32_t a[4], const uint32_t b[2]) {
    asm volatile(
        "mma.sync.aligned.m16n8k8.row.col.f32.tf32.tf32.f32 "
        "{%0,%1,%2,%3}, {%4,%5,%6,%7}, {%8,%9}, {%0,%1,%2,%3};"
        : "+f"(c[0]), "+f"(c[1]), "+f"(c[2]), "+f"(c[3])
        : "r"(a[0]), "r"(a[1]), "r"(a[2]), "r"(a[3]), "r"(b[0]), "r"(b[1]));
}

template <int CIN, int PHASE>
__global__ __launch_bounds__(256) void mma_gemm(const float* __restrict__ xin) {
    extern __shared__ float dsm[];
    float* sA = dsm;
    float* sB = dsm + NSTG * ABUF;
    float* sred = sB;

    const int tid  = threadIdx.x;
    const int wid  = tid >> 5;
    const int lane = tid & 31;
    const int wm = wid >> 1;
    const int wn = wid & 1;
    const int gq = lane >> 2;
    const int tg = lane & 3;

    const int bb = blockIdx.y;
    const int n0 = blockIdx.x * 128;

    const float* Ap   = PHASE ? g_w2p : g_w1p;
    const float* bias = PHASE ? g_b2f : g_b1f;
    float*       out  = PHASE ? g_enh : g_fe;
    const float* xb   = xin   + (size_t)bb * Cc * HWc;
    const float* aggb = g_agg + (size_t)bb * Cc * HWc;

    uint32_t sAa, sBa;
    asm("{ .reg .u64 t; cvta.to.shared.u64 t, %1; cvt.u32.u64 %0, t; }" : "=r"(sAa) : "l"(sA));
    asm("{ .reg .u64 t; cvta.to.shared.u64 t, %1; cvt.u32.u64 %0, t; }" : "=r"(sBa) : "l"(sB));

    auto fill = [&](int ci) {
        const int buf = ci & (NSTG - 1);
        const int k0 = ci * BK;
        const uint32_t sAb = sAa + buf * (ABUF * 4);
        const uint32_t sBb = sBa + buf * (BBUF * 4);
#pragma unroll
        for (int it = 0; it < 4; it++) {
            int id = it * 256 + tid;
            const float* gp = &Ap[(size_t)ci * 4096 + id * 4];
            asm volatile("cp.async.cg.shared.global [%0], [%1], 16;"
                         :: "r"(sAb + (uint32_t)id * 16), "l"(gp));
        }
#pragma unroll
        for (int it = 0; it < 2; it++) {
            int id = it * 256 + tid;
            int kr = id >> 5, q = id & 31;
            int kg = k0 + kr;
            const float* brow;
            if (PHASE == 0) brow = xb + (size_t)kg * HWc;
            else            brow = (kg < Cc) ? xb + (size_t)kg * HWc
                                             : aggb + (size_t)(kg - Cc) * HWc;
            const float* gp = &brow[n0 + q * 4];
            uint32_t s = sBb + (uint32_t)(kr * PADB + q * 4) * 4;
            asm volatile("cp.async.cg.shared.global [%0], [%1], 16;" :: "r"(s), "l"(gp));
        }
        asm volatile("cp.async.commit_group;" ::: "memory");
    };

    float acc[4][8][4];
#pragma unroll
    for (int mt = 0; mt < 4; mt++)
#pragma unroll
        for (int nt = 0; nt < 8; nt++)
#pragma unroll
            for (int i = 0; i < 4; i++) acc[mt][nt][i] = 0.f;

    constexpr int NC = CIN / BK;
    fill(0); fill(1); fill(2);

    for (int ci = 0; ci < NC; ci++) {
        const int rem = NC - 1 - ci;
        if (rem >= 2)      asm volatile("cp.async.wait_group 2;" ::: "memory");
        else if (rem == 1) asm volatile("cp.async.wait_group 1;" ::: "memory");
        else               asm volatile("cp.async.wait_group 0;" ::: "memory");
        __syncthreads();
        if (ci + 3 < NC) fill(ci + 3);

        const int buf = ci & (NSTG - 1);
        const float* A_ = sA + buf * ABUF;
        const float* B_ = sB + buf * BBUF;

        // ---- load ALL fragments for BK=16 first (one big independent batch)
        uint32_t afr[4][2][4];
#pragma unroll
        for (int mt = 0; mt < 4; mt++) {
            int tile = wm * 4 + mt;
#pragma unroll
            for (int k8 = 0; k8 < 2; k8++) {
                const float4 v = *(const float4*)&A_[(tile * 2 + k8) * 128 + lane * 4];
                afr[mt][k8][0] = __float_as_uint(v.x);
                afr[mt][k8][1] = __float_as_uint(v.y);
                afr[mt][k8][2] = __float_as_uint(v.z);
                afr[mt][k8][3] = __float_as_uint(v.w);
            }
        }
        uint32_t bfr[8][2][2];
#pragma unroll
        for (int nt = 0; nt < 8; nt++) {
            int col = wn * 64 + nt * 8 + gq;
#pragma unroll
            for (int k8 = 0; k8 < 2; k8++) {
                bfr[nt][k8][0] = __float_as_uint(B_[(k8 * 8 + tg) * PADB + col]);
                bfr[nt][k8][1] = __float_as_uint(B_[(k8 * 8 + 4 + tg) * PADB + col]);
            }
        }
        // ---- 64 back-to-back HMMAs
#pragma unroll
        for (int k8 = 0; k8 < 2; k8++)
#pragma unroll
            for (int mt = 0; mt < 4; mt++)
#pragma unroll
                for (int nt = 0; nt < 8; nt++)
                    mma_tf32(acc[mt][nt], afr[mt][k8], bfr[nt][k8]);
    }
    __syncthreads();

    // ---------------- epilogue: bias + relu + store + fused reduction ----------
    float ssq[8][2];
    float prt[4][2];
    if (PHASE == 0) {
#pragma unroll
        for (int nt = 0; nt < 8; nt++) { ssq[nt][0] = 0.f; ssq[nt][1] = 0.f; }
    } else {
#pragma unroll
        for (int mt = 0; mt < 4; mt++) { prt[mt][0] = 0.f; prt[mt][1] = 0.f; }
    }

#pragma unroll
    for (int mt = 0; mt < 4; mt++) {
        int row0 = wm * 64 + mt * 16 + gq;
        float bs0 = bias[row0];
        float bs1 = bias[row0 + 8];
        float* o0 = out + ((size_t)bb * Cc + row0) * HWc + n0;
        float* o1 = o0 + 8 * HWc;
#pragma unroll
        for (int nt = 0; nt < 8; nt++) {
            int col = wn * 64 + nt * 8 + 2 * tg;
            float v0x = fmaxf(acc[mt][nt][0] + bs0, 0.f);
            float v0y = fmaxf(acc[mt][nt][1] + bs0, 0.f);
            float v1x = fmaxf(acc[mt][nt][2] + bs1, 0.f);
            float v1y = fmaxf(acc[mt][nt][3] + bs1, 0.f);
            float2 a = {v0x, v0y}, b2 = {v1x, v1y};
            *(float2*)&o0[col] = a;
            *(float2*)&o1[col] = b2;
            if (PHASE == 0) {
                ssq[nt][0] += v0x * v0x + v1x * v1x;
                ssq[nt][1] += v0y * v0y + v1y * v1y;
            } else {
                prt[mt][0] += v0x + v0y;
                prt[mt][1] += v1x + v1y;
            }
        }
    }

    if (PHASE == 0) {
#pragma unroll
        for (int nt = 0; nt < 8; nt++) {
#pragma unroll
            for (int off = 16; off >= 4; off >>= 1) {
                ssq[nt][0] += __shfl_down_sync(0xffffffffu, ssq[nt][0], off);
                ssq[nt][1] += __shfl_down_sync(0xffffffffu, ssq[nt][1], off);
            }
        }
        if (lane < 4) {
#pragma unroll
            for (int nt = 0; nt < 8; nt++) {
                int col = wn * 64 + nt * 8 + 2 * tg;
                sred[wm * 128 + col]     = ssq[nt][0];
                sred[wm * 128 + col + 1] = ssq[nt][1];
            }
        }
        __syncthreads();
        if (tid < 128) {
            float s = sred[tid] + sred[128 + tid] + sred[256 + tid] + sred[384 + tid];
            g_nrm[bb * HWc + n0 + tid] = sqrtf(s);
        }
    } else {
#pragma unroll
        for (int mt = 0; mt < 4; mt++) {
            prt[mt][0] += __shfl_down_sync(0xffffffffu, prt[mt][0], 2);
            prt[mt][0] += __shfl_down_sync(0xffffffffu, prt[mt][0], 1);
            prt[mt][1] += __shfl_down_sync(0xffffffffu, prt[mt][1], 2);
            prt[mt][1] += __shfl_down_sync(0xffffffffu, prt[mt][1], 1);
        }
        if (tg == 0) {
#pragma unroll
            for (int mt = 0; mt < 4; mt++) {
                int row0 = wm * 64 + mt * 16 + gq;
                sred[wn * 256 + row0]     = prt[mt][0];
                sred[wn * 256 + row0 + 8] = prt[mt][1];
            }
        }
        __syncthreads();
        if (tid < 256)
            g_poolp[((size_t)bb * 32 + blockIdx.x) * 256 + tid] =
                sred[tid] + sred[256 + tid];
    }
}

// ---------------- phase A: partial cosine dots (precomputed halo offsets) -------
#define TILE 16
#define HALO 18
#define NPIX (HALO * HALO)
#define CKC  16
#define SHSTR 20
__global__ __launch_bounds__(256) void simdot_kernel() {
    __shared__ float sh[NPIX * SHSTR];

    const int b  = blockIdx.z;
    const int sp = blockIdx.y;
    const int t  = blockIdx.x;
    const int h0 = (t >> 2) * TILE;
    const int w0 = (t & 3) * TILE;
    const int lx = threadIdx.x & (TILE - 1);
    const int ly = threadIdx.x / TILE;
    const int pc = ly * HALO + lx;
    const int tid = threadIdx.x;

    const int p1 = tid;
    const int hy1 = p1 / HALO, hx1 = p1 - hy1 * HALO;
    const int gh1 = h0 + hy1 - 1, gw1 = w0 + hx1 - 1;
    const bool v1 = (gh1 >= 0 && gh1 < Hh && gw1 >= 0 && gw1 < Ww);
    const int off1 = v1 ? gh1 * Ww + gw1 : 0;
    const int p2 = tid + 256;
    const bool has2 = (p2 < NPIX);
    bool v2 = false; int off2 = 0;
    if (has2) {
        int hy2 = p2 / HALO, hx2 = p2 - hy2 * HALO;
        int gh2 = h0 + hy2 - 1, gw2 = w0 + hx2 - 1;
        v2 = (gh2 >= 0 && gh2 < Hh && gw2 >= 0 && gw2 < Ww);
        off2 = v2 ? gh2 * Ww + gw2 : 0;
    }

    const float* feb = g_fe + (size_t)b * Cc * HWc;

    float4 dot4[9];
#pragma unroll
    for (int k = 0; k < 9; k++) dot4[k] = make_float4(0.f, 0.f, 0.f, 0.f);

    const int c0 = sp * 64;
    for (int cc = c0; cc < c0 + 64; cc += CKC) {
#pragma unroll
        for (int c = 0; c < CKC; c++) {
            const float* fc = feb + (size_t)(cc + c) * HWc;
            sh[p1 * SHSTR + c] = v1 ? fc[off1] : 0.f;
            if (has2) sh[p2 * SHSTR + c] = v2 ? fc[off2] : 0.f;
        }
        __syncthreads();
#pragma unroll
        for (int c4 = 0; c4 < 4; c4++) {
            float4 ctr = *(const float4*)&sh[(pc + HALO + 1) * SHSTR + c4 * 4];
#pragma unroll
            for (int di = 0; di < 3; di++)
#pragma unroll
                for (int dj = 0; dj < 3; dj++) {
                    float4 nb = *(const float4*)&sh[(pc + di * HALO + dj) * SHSTR + c4 * 4];
                    int k = di * 3 + dj;
                    dot4[k].x += ctr.x * nb.x;
                    dot4[k].y += ctr.y * nb.y;
                    dot4[k].z += ctr.z * nb.z;
                    dot4[k].w += ctr.w * nb.w;
                }
        }
        __syncthreads();
    }

    const int hw = (h0 + ly) * Ww + w0 + lx;
#pragma unroll
    for (int k = 0; k < 9; k++)
        g_dotp[(((size_t)sp * Bq + b) * 9 + k) * HWc + hw] =
            dot4[k].x + dot4[k].y + dot4[k].z + dot4[k].w;
}

// ---------------- phase B: combine partials, cosine + softmax -------------------
__global__ void simsoft_kernel() {
    const int idx = blockIdx.x * 256 + threadIdx.x;
    const int b = idx >> 12;
    const int hw = idx & 4095;
    const int h = hw >> 6, w = hw & 63;

    float s[9];
#pragma unroll
    for (int k = 0; k < 9; k++) {
        float d = 0.f;
#pragma unroll
        for (int sp = 0; sp < 4; sp++)
            d += g_dotp[(((size_t)sp * Bq + b) * 9 + k) * HWc + hw];
        s[k] = d;
    }
    float nc = g_nrm[b * HWc + hw];
#pragma unroll
    for (int k = 0; k < 9; k++) {
        int di = k / 3, dj = k - 3 * di;
        int nh = h + di - 1, nw = w + dj - 1;
        float np = (nh >= 0 && nh < Hh && nw >= 0 && nw < Ww)
                       ? g_nrm[b * HWc + nh * Ww + nw] : 0.f;
        s[k] = s[k] / (nc * np + 1e-7f);
    }
    float mx = s[0];
#pragma unroll
    for (int k = 1; k < 9; k++) mx = fmaxf(mx, s[k]);
    float sum = 0.f;
#pragma unroll
    for (int k = 0; k < 9; k++) { s[k] = expf(s[k] - mx); sum += s[k]; }
    float inv = 1.f / sum;
#pragma unroll
    for (int k = 0; k < 9; k++)
        g_simw[((size_t)b * 9 + k) * HWc + hw] = s[k] * inv;
}

// ---------------- phase C: weighted 3x3 aggregation (precomputed offsets) -------
__global__ __launch_bounds__(256) void agg_kernel(const float* __restrict__ xin) {
    __shared__ float sh[NPIX * SHSTR];

    const int b  = blockIdx.z;
    const int cc = blockIdx.y * CKC;
    const int t  = blockIdx.x;
    const int h0 = (t >> 2) * TILE;
    const int w0 = (t & 3) * TILE;
    const int lx = threadIdx.x & (TILE - 1);
    const int ly = threadIdx.x / TILE;
    const int pc = ly * HALO + lx;
    const int tid = threadIdx.x;

    const int p1 = tid;
    const int hy1 = p1 / HALO, hx1 = p1 - hy1 * HALO;
    const int gh1 = h0 + hy1 - 1, gw1 = w0 + hx1 - 1;
    const bool v1 = (gh1 >= 0 && gh1 < Hh && gw1 >= 0 && gw1 < Ww);
    const int off1 = v1 ? gh1 * Ww + gw1 : 0;
    const int p2 = tid + 256;
    const bool has2 = (p2 < NPIX);
    bool v2 = false; int off2 = 0;
    if (has2) {
        int hy2 = p2 / HALO, hx2 = p2 - hy2 * HALO;
        int gh2 = h0 + hy2 - 1, gw2 = w0 + hx2 - 1;
        v2 = (gh2 >= 0 && gh2 < Hh && gw2 >= 0 && gw2 < Ww);
        off2 = v2 ? gh2 * Ww + gw2 : 0;
    }

    const float* xb = xin + (size_t)b * Cc * HWc;
#pragma unroll
    for (int c = 0; c < CKC; c++) {
        const float* fc = xb + (size_t)(cc + c) * HWc;
        sh[p1 * SHSTR + c] = v1 ? fc[off1] : 0.f;
        if (has2) sh[p2 * SHSTR + c] = v2 ? fc[off2] : 0.f;
    }
    __syncthreads();

    const int hw = (h0 + ly) * Ww + w0 + lx;
    float s[9];
#pragma unroll
    for (int k = 0; k < 9; k++)
        s[k] = g_simw[((size_t)b * 9 + k) * HWc + hw];

    float* aggb = g_agg + (size_t)b * Cc * HWc;
#pragma unroll
    for (int c4 = 0; c4 < 4; c4++) {
        float4 a = make_float4(0.f, 0.f, 0.f, 0.f);
#pragma unroll
        for (int di = 0; di < 3; di++)
#pragma unroll
            for (int dj = 0; dj < 3; dj++) {
                float4 nb = *(const float4*)&sh[(pc + di * HALO + dj) * SHSTR + c4 * 4];
                float wk = s[di * 3 + dj];
                a.x += wk * nb.x;
                a.y += wk * nb.y;
                a.z += wk * nb.z;
                a.w += wk * nb.w;
            }
        size_t base = (size_t)(cc + c4 * 4) * HWc + hw;
        aggb[base]           = a.x;
        aggb[base + HWc]     = a.y;
        aggb[base + 2 * HWc] = a.z;
        aggb[base + 3 * HWc] = a.w;
    }
}

// ---------------- pool of x ------------------------------------------------------
__global__ void poolx_kernel(const float* __restrict__ xin) {
    const int c = blockIdx.x;
    const int b = blockIdx.y;
    const int tid = threadIdx.x;
    const float* src = xin + ((size_t)b * Cc + c) * HWc;
    float s = 0.f;
#pragma unroll
    for (int i = tid * 4; i < HWc; i += 1024) {
        float4 v = *(const float4*)&src[i];
        s += v.x + v.y + v.z + v.w;
    }
#pragma unroll
    for (int o = 16; o > 0; o >>= 1) s += __shfl_down_sync(0xffffffffu, s, o);
    __shared__ float red[8];
    if ((tid & 31) == 0) red[tid >> 5] = s;
    __syncthreads();
    if (tid < 8) {
        float t = red[tid];
#pragma unroll
        for (int o = 4; o > 0; o >>= 1) t += __shfl_down_sync(0xffu, t, o);
        if (tid == 0) g_pool[b * 512 + c] = t * (1.f / HWc);
    }
}

// ---------------- combine enhanced pool partials --------------------------------
__global__ void pool2_kernel() {
    const int b = blockIdx.x;
    const int c = threadIdx.x;
    float s = 0.f;
#pragma unroll 8
    for (int nb = 0; nb < 32; nb++)
        s += g_poolp[((size_t)b * 32 + nb) * 256 + c];
    g_pool[b * 512 + 256 + c] = s * (1.f / HWc);
}

// ---------------- SE gate --------------------------------------------------------
__global__ void gate_kernel(const float* __restrict__ w1, const float* __restrict__ b1,
                            const float* __restrict__ w2, const float* __restrict__ b2) {
    const int b = blockIdx.x;
    const int tid = threadIdx.x;
    __shared__ float sp[512];
    __shared__ float shid[64];
    for (int i = tid; i < 512; i += 256) sp[i] = g_pool[b * 512 + i];
    __syncthreads();
    if (tid < 64) {
        float s = b1[tid];
        const float* wr = w1 + tid * 512;
#pragma unroll 8
        for (int c = 0; c < 512; c++) s += wr[c] * sp[c];
        shid[tid] = fmaxf(s, 0.f);
    }
    __syncthreads();
    float s = b2[tid];
    const float* wr = w2 + tid * 64;
#pragma unroll
    for (int j = 0; j < 64; j++) s += wr[j] * shid[j];
    g_gate[b * 256 + tid] = 1.f / (1.f + expf(-s));
}

// ---------------- residual + gated enhancement ----------------------------------
__global__ void final_kernel(const float* __restrict__ xin, float* __restrict__ out) {
    size_t e = ((size_t)blockIdx.x * blockDim.x + threadIdx.x) * 4;
    if (e >= TOTAL) return;
    int bc = (int)(e >> 12);
    float g = g_gate[bc];
    float4 xv = *(const float4*)&xin[e];
    float4 ev = *(const float4*)&g_enh[e];
    float4 o;
    o.x = xv.x + g * ev.x;
    o.y = xv.y + g * ev.y;
    o.z = xv.z + g * ev.z;
    o.w = xv.w + g * ev.w;
    *(float4*)&out[e] = o;
}

// ---------------- launch ----------------------------------------------------------
extern "C" void kernel_launch(void* const* d_in, const int* in_sizes, int n_in,
                              void* d_out, int out_size) {
    const float* x       = (const float*)d_in[0];
    const float* w_embed = (const float*)d_in[1];
    const float* b_embed = (const float*)d_in[2];
    const float* bn1_g   = (const float*)d_in[3];
    const float* bn1_b   = (const float*)d_in[4];
    const float* bn1_m   = (const float*)d_in[5];
    const float* bn1_v   = (const float*)d_in[6];
    const float* w_enh   = (const float*)d_in[7];
    const float* b_enh   = (const float*)d_in[8];
    const float* bn2_g   = (const float*)d_in[9];
    const float* bn2_b   = (const float*)d_in[10];
    const float* bn2_m   = (const float*)d_in[11];
    const float* bn2_v   = (const float*)d_in[12];
    const float* w_g1    = (const float*)d_in[13];
    const float* b_g1    = (const float*)d_in[14];
    const float* w_g2    = (const float*)d_in[15];
    const float* b_g2    = (const float*)d_in[16];
    float* out = (float*)d_out;

    static bool attr_done = false;
    if (!attr_done) {
        cudaFuncSetAttribute(mma_gemm<256, 0>, cudaFuncAttributeMaxDynamicSharedMemorySize, GSMEM);
        cudaFuncSetAttribute(mma_gemm<512, 1>, cudaFuncAttributeMaxDynamicSharedMemorySize, GSMEM);
        attr_done = true;
    }

    fold_kernel<<<256, 256>>>(w_embed, b_embed, bn1_g, bn1_b, bn1_m, bn1_v, 256, 0);
    fold_kernel<<<256, 256>>>(w_enh,   b_enh,   bn2_g, bn2_b, bn2_m, bn2_v, 512, 1);
    poolx_kernel<<<dim3(256, Bq), 256>>>(x);

    mma_gemm<256, 0><<<dim3(32, Bq), 256, GSMEM>>>(x);          // fe + norm (4th: profiled)
    simdot_kernel<<<dim3(16, 4, Bq), 256>>>();
    simsoft_kernel<<<(Bq * HWc) / 256, 256>>>();
    agg_kernel<<<dim3(16, Cc / CKC, Bq), 256>>>(x);
    mma_gemm<512, 1><<<dim3(32, Bq), 256, GSMEM>>>(x);          // enhanced + pool partials

    pool2_kernel<<<Bq, 256>>>();
    gate_kernel<<<Bq, 256>>>(w_g1, b_g1, w_g2, b_g2);
    final_kernel<<<(unsigned)(TOTAL / 4 / 256), 256>>>(x, out);
}

// round 11
// speedup vs baseline: 1.0667x; 1.0667x over previous
#include <cuda_runtime.h>
#include <cstdint>
#include <cstddef>

#define Bq   8
#define Cc   256
#define Hh   64
#define Ww   64
#define HWc  4096
#define TOTAL (8UL*256*4096)

// ---------------- scratch (device globals) ------------------------------------
__device__ float g_fe  [TOTAL];
__device__ float g_agg [TOTAL];
__device__ float g_enh [TOTAL];
__device__ float g_part[TOTAL];        // W2x . x (raw, no bias)
__device__ float g_w1p [256*256];      // fragment-ready folded embed weight
__device__ float g_w2p [256*512];      // fragment-ready folded enhance weight
__device__ float g_b1f [256];
__device__ float g_b2f [256];
__device__ float g_nrm [Bq*HWc];
__device__ float g_dotp[4*Bq*9*HWc];
__device__ float g_simw[Bq*9*HWc];
__device__ float g_poolp[Bq*32*256];
__device__ float g_pool[Bq*512];
__device__ float g_gate[Bq*256];

// ---------------- BN fold -> fragment-ready permuted layout --------------------
__global__ void fold_kernel(const float* __restrict__ w, const float* __restrict__ bsrc,
                            const float* __restrict__ gm, const float* __restrict__ bt,
                            const float* __restrict__ mn, const float* __restrict__ vr,
                            int cin, int which) {
    int o = blockIdx.x;
    float inv = gm[o] * rsqrtf(vr[o] + 1e-5f);
    float* wp = which ? g_w2p : g_w1p;
    float* bf = which ? g_b2f : g_b1f;
    const int tile = o >> 4;
    const int r = o & 15;
    const int gqv = r & 7;
    const int hi = r >> 3;
    for (int k = threadIdx.x; k < cin; k += blockDim.x) {
        int ci = k >> 4, kk = k & 15;
        int k8 = kk >> 3, kw = kk & 7;
        int lane = gqv * 4 + (kw & 3);
        int e = hi + ((kw >> 2) << 1);
        wp[(size_t)ci * 4096 + tile * 256 + k8 * 128 + lane * 4 + e] = inv * w[o * cin + k];
    }
    if (threadIdx.x == 0)
        bf[o] = bsrc[o] * inv + bt[o] - mn[o] * inv;
}

// ---------------- mma.sync tf32 GEMM (R9 mainloop, NC=16 always) ---------------
// PHASE 0: fe = relu(W1.x + b1), + per-pixel norm over 256 channels
// PHASE 2: part = W2x . x          (raw, no bias/relu)
// PHASE 3: enh = relu(W2a.agg + part + b2), + pool partials
#define BK   16
#define PADB 136
#define NSTG 4
#define ABUF 4096
#define BBUF (BK * PADB)
#define GSMEM (NSTG * (ABUF + BBUF) * 4)   // 100352 B

__device__ __forceinline__ void mma_tf32(float c[4], const uint32_t a[4], const uint32_t b[2]) {
    asm volatile(
        "mma.sync.aligned.m16n8k8.row.col.f32.tf32.tf32.f32 "
        "{%0,%1,%2,%3}, {%4,%5,%6,%7}, {%8,%9}, {%0,%1,%2,%3};"
        : "+f"(c[0]), "+f"(c[1]), "+f"(c[2]), "+f"(c[3])
        : "r"(a[0]), "r"(a[1]), "r"(a[2]), "r"(a[3]), "r"(b[0]), "r"(b[1]));
}

template <int PHASE>
__global__ __launch_bounds__(256) void mma_gemm(const float* __restrict__ xin) {
    extern __shared__ float dsm[];
    float* sA = dsm;
    float* sB = dsm + NSTG * ABUF;
    float* sred = sB;

    const int tid  = threadIdx.x;
    const int wid  = tid >> 5;
    const int lane = tid & 31;
    const int wm = wid >> 1;
    const int wn = wid & 1;
    const int gq = lane >> 2;
    const int tg = lane & 3;

    const int bb = blockIdx.y;
    const int n0 = blockIdx.x * 128;

    const float* Ap   = (PHASE == 0) ? g_w1p : (PHASE == 2) ? g_w2p : (g_w2p + 16 * 4096);
    const float* bias = (PHASE == 0) ? g_b1f : g_b2f;
    float*       out  = (PHASE == 0) ? g_fe : (PHASE == 2) ? g_part : g_enh;
    const float* Bsrc = (PHASE == 3) ? (g_agg + (size_t)bb * Cc * HWc)
                                     : (xin   + (size_t)bb * Cc * HWc);

    uint32_t sAa, sBa;
    asm("{ .reg .u64 t; cvta.to.shared.u64 t, %1; cvt.u32.u64 %0, t; }" : "=r"(sAa) : "l"(sA));
    asm("{ .reg .u64 t; cvta.to.shared.u64 t, %1; cvt.u32.u64 %0, t; }" : "=r"(sBa) : "l"(sB));

    auto fill = [&](int ci) {
        const int buf = ci & (NSTG - 1);
        const int k0 = ci * BK;
        const uint32_t sAb = sAa + buf * (ABUF * 4);
        const uint32_t sBb = sBa + buf * (BBUF * 4);
#pragma unroll
        for (int it = 0; it < 4; it++) {
            int id = it * 256 + tid;
            const float* gp = &Ap[(size_t)ci * 4096 + id * 4];
            asm volatile("cp.async.cg.shared.global [%0], [%1], 16;"
                         :: "r"(sAb + (uint32_t)id * 16), "l"(gp));
        }
#pragma unroll
        for (int it = 0; it < 2; it++) {
            int id = it * 256 + tid;
            int kr = id >> 5, q = id & 31;
            const float* gp = &Bsrc[(size_t)(k0 + kr) * HWc + n0 + q * 4];
            uint32_t s = sBb + (uint32_t)(kr * PADB + q * 4) * 4;
            asm volatile("cp.async.cg.shared.global [%0], [%1], 16;" :: "r"(s), "l"(gp));
        }
        asm volatile("cp.async.commit_group;" ::: "memory");
    };

    float acc[4][8][4];
#pragma unroll
    for (int mt = 0; mt < 4; mt++)
#pragma unroll
        for (int nt = 0; nt < 8; nt++)
#pragma unroll
            for (int i = 0; i < 4; i++) acc[mt][nt][i] = 0.f;

    constexpr int NC = 16;
    fill(0); fill(1); fill(2);

    for (int ci = 0; ci < NC; ci++) {
        const int rem = NC - 1 - ci;
        if (rem >= 2)      asm volatile("cp.async.wait_group 2;" ::: "memory");
        else if (rem == 1) asm volatile("cp.async.wait_group 1;" ::: "memory");
        else               asm volatile("cp.async.wait_group 0;" ::: "memory");
        __syncthreads();
        if (ci + 3 < NC) fill(ci + 3);

        const int buf = ci & (NSTG - 1);
        const float* A_ = sA + buf * ABUF;
        const float* B_ = sB + buf * BBUF;
#pragma unroll
        for (int k8 = 0; k8 < 2; k8++) {
            const int kb = k8 * 8;
            uint32_t afr[4][4];
#pragma unroll
            for (int mt = 0; mt < 4; mt++) {
                int tile = wm * 4 + mt;
                const float4 v = *(const float4*)&A_[(tile * 2 + k8) * 128 + lane * 4];
                afr[mt][0] = __float_as_uint(v.x);
                afr[mt][1] = __float_as_uint(v.y);
                afr[mt][2] = __float_as_uint(v.z);
                afr[mt][3] = __float_as_uint(v.w);
            }
            uint32_t bfr[8][2];
#pragma unroll
            for (int nt = 0; nt < 8; nt++) {
                int col = wn * 64 + nt * 8 + gq;
                bfr[nt][0] = __float_as_uint(B_[(kb + tg) * PADB + col]);
                bfr[nt][1] = __float_as_uint(B_[(kb + 4 + tg) * PADB + col]);
            }
#pragma unroll
            for (int mt = 0; mt < 4; mt++)
#pragma unroll
                for (int nt = 0; nt < 8; nt++)
                    mma_tf32(acc[mt][nt], afr[mt], bfr[nt]);
        }
    }
    __syncthreads();

    // ---------------- epilogue ---------------------------------------------------
    float ssq[8][2];
    float prt[4][2];
    if (PHASE == 0) {
#pragma unroll
        for (int nt = 0; nt < 8; nt++) { ssq[nt][0] = 0.f; ssq[nt][1] = 0.f; }
    } else if (PHASE == 3) {
#pragma unroll
        for (int mt = 0; mt < 4; mt++) { prt[mt][0] = 0.f; prt[mt][1] = 0.f; }
    }

#pragma unroll
    for (int mt = 0; mt < 4; mt++) {
        int row0 = wm * 64 + mt * 16 + gq;
        float bs0 = (PHASE == 2) ? 0.f : bias[row0];
        float bs1 = (PHASE == 2) ? 0.f : bias[row0 + 8];
        float* o0 = out + ((size_t)bb * Cc + row0) * HWc + n0;
        float* o1 = o0 + 8 * HWc;
        const float* p0 = g_part + ((size_t)bb * Cc + row0) * HWc + n0;
        const float* p1 = p0 + 8 * HWc;
#pragma unroll
        for (int nt = 0; nt < 8; nt++) {
            int col = wn * 64 + nt * 8 + 2 * tg;
            float v0x, v0y, v1x, v1y;
            if (PHASE == 2) {
                v0x = acc[mt][nt][0]; v0y = acc[mt][nt][1];
                v1x = acc[mt][nt][2]; v1y = acc[mt][nt][3];
            } else if (PHASE == 3) {
                float2 q0 = *(const float2*)&p0[col];
                float2 q1 = *(const float2*)&p1[col];
                v0x = fmaxf(acc[mt][nt][0] + q0.x + bs0, 0.f);
                v0y = fmaxf(acc[mt][nt][1] + q0.y + bs0, 0.f);
                v1x = fmaxf(acc[mt][nt][2] + q1.x + bs1, 0.f);
                v1y = fmaxf(acc[mt][nt][3] + q1.y + bs1, 0.f);
            } else {
                v0x = fmaxf(acc[mt][nt][0] + bs0, 0.f);
                v0y = fmaxf(acc[mt][nt][1] + bs0, 0.f);
                v1x = fmaxf(acc[mt][nt][2] + bs1, 0.f);
                v1y = fmaxf(acc[mt][nt][3] + bs1, 0.f);
            }
            float2 a = {v0x, v0y}, b2 = {v1x, v1y};
            *(float2*)&o0[col] = a;
            *(float2*)&o1[col] = b2;
            if (PHASE == 0) {
                ssq[nt][0] += v0x * v0x + v1x * v1x;
                ssq[nt][1] += v0y * v0y + v1y * v1y;
            } else if (PHASE == 3) {
                prt[mt][0] += v0x + v0y;
                prt[mt][1] += v1x + v1y;
            }
        }
    }

    if (PHASE == 0) {
#pragma unroll
        for (int nt = 0; nt < 8; nt++) {
#pragma unroll
            for (int off = 16; off >= 4; off >>= 1) {
                ssq[nt][0] += __shfl_down_sync(0xffffffffu, ssq[nt][0], off);
                ssq[nt][1] += __shfl_down_sync(0xffffffffu, ssq[nt][1], off);
            }
        }
        if (lane < 4) {
#pragma unroll
            for (int nt = 0; nt < 8; nt++) {
                int col = wn * 64 + nt * 8 + 2 * tg;
                sred[wm * 128 + col]     = ssq[nt][0];
                sred[wm * 128 + col + 1] = ssq[nt][1];
            }
        }
        __syncthreads();
        if (tid < 128) {
            float s = sred[tid] + sred[128 + tid] + sred[256 + tid] + sred[384 + tid];
            g_nrm[bb * HWc + n0 + tid] = sqrtf(s);
        }
    } else if (PHASE == 3) {
#pragma unroll
        for (int mt = 0; mt < 4; mt++) {
            prt[mt][0] += __shfl_down_sync(0xffffffffu, prt[mt][0], 2);
            prt[mt][0] += __shfl_down_sync(0xffffffffu, prt[mt][0], 1);
            prt[mt][1] += __shfl_down_sync(0xffffffffu, prt[mt][1], 2);
            prt[mt][1] += __shfl_down_sync(0xffffffffu, prt[mt][1], 1);
        }
        if (tg == 0) {
#pragma unroll
            for (int mt = 0; mt < 4; mt++) {
                int row0 = wm * 64 + mt * 16 + gq;
                sred[wn * 256 + row0]     = prt[mt][0];
                sred[wn * 256 + row0 + 8] = prt[mt][1];
            }
        }
        __syncthreads();
        if (tid < 256)
            g_poolp[((size_t)bb * 32 + blockIdx.x) * 256 + tid] =
                sred[tid] + sred[256 + tid];
    }
}

// ---------------- phase A: partial cosine dots (R9 version) ---------------------
#define TILE 16
#define HALO 18
#define NPIX (HALO * HALO)
#define CKC  16
#define SHSTR 20
__global__ __launch_bounds__(256) void simdot_kernel() {
    __shared__ float sh[NPIX * SHSTR];

    const int b  = blockIdx.z;
    const int sp = blockIdx.y;
    const int t  = blockIdx.x;
    const int h0 = (t >> 2) * TILE;
    const int w0 = (t & 3) * TILE;
    const int lx = threadIdx.x & (TILE - 1);
    const int ly = threadIdx.x / TILE;
    const int pc = ly * HALO + lx;

    const float* feb = g_fe + (size_t)b * Cc * HWc;

    float4 dot4[9];
#pragma unroll
    for (int k = 0; k < 9; k++) dot4[k] = make_float4(0.f, 0.f, 0.f, 0.f);

    const int c0 = sp * 64;
    for (int cc = c0; cc < c0 + 64; cc += CKC) {
        for (int idx = threadIdx.x; idx < CKC * NPIX; idx += 256) {
            int c = idx / NPIX;
            int p = idx - c * NPIX;
            int hy = p / HALO, hx = p - hy * HALO;
            int gh = h0 + hy - 1, gw = w0 + hx - 1;
            float v = 0.f;
            if (gh >= 0 && gh < Hh && gw >= 0 && gw < Ww)
                v = feb[(size_t)(cc + c) * HWc + gh * Ww + gw];
            sh[p * SHSTR + c] = v;
        }
        __syncthreads();
#pragma unroll
        for (int c4 = 0; c4 < 4; c4++) {
            float4 ctr = *(const float4*)&sh[(pc + HALO + 1) * SHSTR + c4 * 4];
#pragma unroll
            for (int di = 0; di < 3; di++)
#pragma unroll
                for (int dj = 0; dj < 3; dj++) {
                    float4 nb = *(const float4*)&sh[(pc + di * HALO + dj) * SHSTR + c4 * 4];
                    int k = di * 3 + dj;
                    dot4[k].x += ctr.x * nb.x;
                    dot4[k].y += ctr.y * nb.y;
                    dot4[k].z += ctr.z * nb.z;
                    dot4[k].w += ctr.w * nb.w;
                }
        }
        __syncthreads();
    }

    const int hw = (h0 + ly) * Ww + w0 + lx;
#pragma unroll
    for (int k = 0; k < 9; k++)
        g_dotp[(((size_t)sp * Bq + b) * 9 + k) * HWc + hw] =
            dot4[k].x + dot4[k].y + dot4[k].z + dot4[k].w;
}

// ---------------- phase B: combine partials, cosine + softmax -------------------
__global__ void simsoft_kernel() {
    const int idx = blockIdx.x * 256 + threadIdx.x;
    const int b = idx >> 12;
    const int hw = idx & 4095;
    const int h = hw >> 6, w = hw & 63;

    float s[9];
#pragma unroll
    for (int k = 0; k < 9; k++) {
        float d = 0.f;
#pragma unroll
        for (int sp = 0; sp < 4; sp++)
            d += g_dotp[(((size_t)sp * Bq + b) * 9 + k) * HWc + hw];
        s[k] = d;
    }
    float nc = g_nrm[b * HWc + hw];
#pragma unroll
    for (int k = 0; k < 9; k++) {
        int di = k / 3, dj = k - 3 * di;
        int nh = h + di - 1, nw = w + dj - 1;
        float np = (nh >= 0 && nh < Hh && nw >= 0 && nw < Ww)
                       ? g_nrm[b * HWc + nh * Ww + nw] : 0.f;
        s[k] = s[k] / (nc * np + 1e-7f);
    }
    float mx = s[0];
#pragma unroll
    for (int k = 1; k < 9; k++) mx = fmaxf(mx, s[k]);
    float sum = 0.f;
#pragma unroll
    for (int k = 0; k < 9; k++) { s[k] = expf(s[k] - mx); sum += s[k]; }
    float inv = 1.f / sum;
#pragma unroll
    for (int k = 0; k < 9; k++)
        g_simw[((size_t)b * 9 + k) * HWc + hw] = s[k] * inv;
}

// ---------------- phase C: weighted 3x3 aggregation (R9 version) ----------------
__global__ __launch_bounds__(256) void agg_kernel(const float* __restrict__ xin) {
    __shared__ float sh[NPIX * SHSTR];

    const int b  = blockIdx.z;
    const int cc = blockIdx.y * CKC;
    const int t  = blockIdx.x;
    const int h0 = (t >> 2) * TILE;
    const int w0 = (t & 3) * TILE;
    const int lx = threadIdx.x & (TILE - 1);
    const int ly = threadIdx.x / TILE;
    const int pc = ly * HALO + lx;

    const float* xb = xin + (size_t)b * Cc * HWc;

    for (int idx = threadIdx.x; idx < CKC * NPIX; idx += 256) {
        int c = idx / NPIX;
        int p = idx - c * NPIX;
        int hy = p / HALO, hx = p - hy * HALO;
        int gh = h0 + hy - 1, gw = w0 + hx - 1;
        float v = 0.f;
        if (gh >= 0 && gh < Hh && gw >= 0 && gw < Ww)
            v = xb[(size_t)(cc + c) * HWc + gh * Ww + gw];
        sh[p * SHSTR + c] = v;
    }
    __syncthreads();

    const int hw = (h0 + ly) * Ww + w0 + lx;
    float s[9];
#pragma unroll
    for (int k = 0; k < 9; k++)
        s[k] = g_simw[((size_t)b * 9 + k) * HWc + hw];

    float* aggb = g_agg + (size_t)b * Cc * HWc;
#pragma unroll
    for (int c4 = 0; c4 < 4; c4++) {
        float4 a = make_float4(0.f, 0.f, 0.f, 0.f);
#pragma unroll
        for (int di = 0; di < 3; di++)
#pragma unroll
            for (int dj = 0; dj < 3; dj++) {
                float4 nb = *(const float4*)&sh[(pc + di * HALO + dj) * SHSTR + c4 * 4];
                float wk = s[di * 3 + dj];
                a.x += wk * nb.x;
                a.y += wk * nb.y;
                a.z += wk * nb.z;
                a.w += wk * nb.w;
            }
        size_t base = (size_t)(cc + c4 * 4) * HWc + hw;
        aggb[base]           = a.x;
        aggb[base + HWc]     = a.y;
        aggb[base + 2 * HWc] = a.z;
        aggb[base + 3 * HWc] = a.w;
    }
}

// ---------------- pool of x ------------------------------------------------------
__global__ void poolx_kernel(const float* __restrict__ xin) {
    const int c = blockIdx.x;
    const int b = blockIdx.y;
    const int tid = threadIdx.x;
    const float* src = xin + ((size_t)b * Cc + c) * HWc;
    float s = 0.f;
#pragma unroll
    for (int i = tid * 4; i < HWc; i += 1024) {
        float4 v = *(const float4*)&src[i];
        s += v.x + v.y + v.z + v.w;
    }
#pragma unroll
    for (int o = 16; o > 0; o >>= 1) s += __shfl_down_sync(0xffffffffu, s, o);
    __shared__ float red[8];
    if ((tid & 31) == 0) red[tid >> 5] = s;
    __syncthreads();
    if (tid < 8) {
        float t = red[tid];
#pragma unroll
        for (int o = 4; o > 0; o >>= 1) t += __shfl_down_sync(0xffu, t, o);
        if (tid == 0) g_pool[b * 512 + c] = t * (1.f / HWc);
    }
}

// ---------------- combine enhanced pool partials --------------------------------
__global__ void pool2_kernel() {
    const int b = blockIdx.x;
    const int c = threadIdx.x;
    float s = 0.f;
#pragma unroll 8
    for (int nb = 0; nb < 32; nb++)
        s += g_poolp[((size_t)b * 32 + nb) * 256 + c];
    g_pool[b * 512 + 256 + c] = s * (1.f / HWc);
}

// ---------------- SE gate --------------------------------------------------------
__global__ void gate_kernel(const float* __restrict__ w1, const float* __restrict__ b1,
                            const float* __restrict__ w2, const float* __restrict__ b2) {
    const int b = blockIdx.x;
    const int tid = threadIdx.x;
    __shared__ float sp[512];
    __shared__ float shid[64];
    for (int i = tid; i < 512; i += 256) sp[i] = g_pool[b * 512 + i];
    __syncthreads();
    if (tid < 64) {
        float s = b1[tid];
        const float* wr = w1 + tid * 512;
#pragma unroll 8
        for (int c = 0; c < 512; c++) s += wr[c] * sp[c];
        shid[tid] = fmaxf(s, 0.f);
    }
    __syncthreads();
    float s = b2[tid];
    const float* wr = w2 + tid * 64;
#pragma unroll
    for (int j = 0; j < 64; j++) s += wr[j] * shid[j];
    g_gate[b * 256 + tid] = 1.f / (1.f + expf(-s));
}

// ---------------- residual + gated enhancement ----------------------------------
__global__ void final_kernel(const float* __restrict__ xin, float* __restrict__ out) {
    size_t e = ((size_t)blockIdx.x * blockDim.x + threadIdx.x) * 4;
    if (e >= TOTAL) return;
    int bc = (int)(e >> 12);
    float g = g_gate[bc];
    float4 xv = *(const float4*)&xin[e];
    float4 ev = *(const float4*)&g_enh[e];
    float4 o;
    o.x = xv.x + g * ev.x;
    o.y = xv.y + g * ev.y;
    o.z = xv.z + g * ev.z;
    o.w = xv.w + g * ev.w;
    *(float4*)&out[e] = o;
}

// ---------------- launch ----------------------------------------------------------
extern "C" void kernel_launch(void* const* d_in, const int* in_sizes, int n_in,
                              void* d_out, int out_size) {
    const float* x       = (const float*)d_in[0];
    const float* w_embed = (const float*)d_in[1];
    const float* b_embed = (const float*)d_in[2];
    const float* bn1_g   = (const float*)d_in[3];
    const float* bn1_b   = (const float*)d_in[4];
    const float* bn1_m   = (const float*)d_in[5];
    const float* bn1_v   = (const float*)d_in[6];
    const float* w_enh   = (const float*)d_in[7];
    const float* b_enh   = (const float*)d_in[8];
    const float* bn2_g   = (const float*)d_in[9];
    const float* bn2_b   = (const float*)d_in[10];
    const float* bn2_m   = (const float*)d_in[11];
    const float* bn2_v   = (const float*)d_in[12];
    const float* w_g1    = (const float*)d_in[13];
    const float* b_g1    = (const float*)d_in[14];
    const float* w_g2    = (const float*)d_in[15];
    const float* b_g2    = (const float*)d_in[16];
    float* out = (float*)d_out;

    static cudaStream_t s2;
    static cudaEvent_t evFold, evSide;
    static bool init_done = false;
    if (!init_done) {
        cudaFuncSetAttribute(mma_gemm<0>, cudaFuncAttributeMaxDynamicSharedMemorySize, GSMEM);
        cudaFuncSetAttribute(mma_gemm<2>, cudaFuncAttributeMaxDynamicSharedMemorySize, GSMEM);
        cudaFuncSetAttribute(mma_gemm<3>, cudaFuncAttributeMaxDynamicSharedMemorySize, GSMEM);
        cudaStreamCreateWithFlags(&s2, cudaStreamNonBlocking);
        cudaEventCreateWithFlags(&evFold, cudaEventDisableTiming);
        cudaEventCreateWithFlags(&evSide, cudaEventDisableTiming);
        init_done = true;
    }

    fold_kernel<<<256, 256>>>(w_embed, b_embed, bn1_g, bn1_b, bn1_m, bn1_v, 256, 0);
    fold_kernel<<<256, 256>>>(w_enh,   b_enh,   bn2_g, bn2_b, bn2_m, bn2_v, 512, 1);

    // fork: side stream computes part = W2x.x and pool(x) concurrently
    cudaEventRecord(evFold, 0);
    cudaStreamWaitEvent(s2, evFold, 0);
    mma_gemm<2><<<dim3(32, Bq), 256, GSMEM, s2>>>(x);           // part
    poolx_kernel<<<dim3(256, Bq), 256, 0, s2>>>(x);
    cudaEventRecord(evSide, s2);

    // main chain
    mma_gemm<0><<<dim3(32, Bq), 256, GSMEM>>>(x);               // fe + norm
    simdot_kernel<<<dim3(16, 4, Bq), 256>>>();
    simsoft_kernel<<<(Bq * HWc) / 256, 256>>>();
    agg_kernel<<<dim3(16, Cc / CKC, Bq), 256>>>(x);

    // join: need part before gemm2b
    cudaStreamWaitEvent(0, evSide, 0);
    mma_gemm<3><<<dim3(32, Bq), 256, GSMEM>>>(x);               // enhanced + pool partials

    pool2_kernel<<<Bq, 256>>>();
    gate_kernel<<<Bq, 256>>>(w_g1, b_g1, w_g2, b_g2);
    final_kernel<<<(unsigned)(TOTAL / 4 / 256), 256>>>(x, out);
}

// round 12
// speedup vs baseline: 1.1627x; 1.0900x over previous
#include <cuda_runtime.h>
#include <cstdint>
#include <cstddef>

#define Bq   8
#define Cc   256
#define Hh   64
#define Ww   64
#define HWc  4096
#define TOTAL (8UL*256*4096)

// ---------------- scratch (device globals) ------------------------------------
__device__ float g_fe  [TOTAL];
__device__ float g_agg [TOTAL];
__device__ float g_enh [TOTAL];
__device__ float g_w1p [256*256];      // fragment-ready folded embed weight
__device__ float g_w2p [256*512];      // fragment-ready folded enhance weight
__device__ float g_b1f [256];
__device__ float g_b2f [256];
__device__ float g_nrm [Bq*HWc];
__device__ float g_dotp[8*Bq*9*HWc];   // partial dots [split][b][9][hw]
__device__ float g_simw[Bq*9*HWc];     // softmax weights [b][9][hw]
__device__ float g_poolp[Bq*32*256];
__device__ float g_pool[Bq*512];
__device__ float g_gate[Bq*256];

// ---------------- BN fold -> fragment-ready permuted layout --------------------
__global__ void fold_kernel(const float* __restrict__ w, const float* __restrict__ bsrc,
                            const float* __restrict__ gm, const float* __restrict__ bt,
                            const float* __restrict__ mn, const float* __restrict__ vr,
                            int cin, int which) {
    int o = blockIdx.x;
    float inv = gm[o] * rsqrtf(vr[o] + 1e-5f);
    float* wp = which ? g_w2p : g_w1p;
    float* bf = which ? g_b2f : g_b1f;
    const int tile = o >> 4;
    const int r = o & 15;
    const int gqv = r & 7;
    const int hi = r >> 3;
    for (int k = threadIdx.x; k < cin; k += blockDim.x) {
        int ci = k >> 4, kk = k & 15;
        int k8 = kk >> 3, kw = kk & 7;
        int lane = gqv * 4 + (kw & 3);
        int e = hi + ((kw >> 2) << 1);
        wp[(size_t)ci * 4096 + tile * 256 + k8 * 128 + lane * 4 + e] = inv * w[o * cin + k];
    }
    if (threadIdx.x == 0)
        bf[o] = bsrc[o] * inv + bt[o] - mn[o] * inv;
}

// ---------------- mma.sync tf32 GEMM (R9 version) -------------------------------
#define BK   16
#define PADB 136
#define NSTG 4
#define ABUF 4096
#define BBUF (BK * PADB)
#define GSMEM (NSTG * (ABUF + BBUF) * 4)   // 100352 B

__device__ __forceinline__ void mma_tf32(float c[4], const uint32_t a[4], const uint32_t b[2]) {
    asm volatile(
        "mma.sync.aligned.m16n8k8.row.col.f32.tf32.tf32.f32 "
        "{%0,%1,%2,%3}, {%4,%5,%6,%7}, {%8,%9}, {%0,%1,%2,%3};"
        : "+f"(c[0]), "+f"(c[1]), "+f"(c[2]), "+f"(c[3])
        : "r"(a[0]), "r"(a[1]), "r"(a[2]), "r"(a[3]), "r"(b[0]), "r"(b[1]));
}

template <int CIN, int PHASE>
__global__ __launch_bounds__(256) void mma_gemm(const float* __restrict__ xin) {
    extern __shared__ float dsm[];
    float* sA = dsm;
    float* sB = dsm + NSTG * ABUF;
    float* sred = sB;

    const int tid  = threadIdx.x;
    const int wid  = tid >> 5;
    const int lane = tid & 31;
    const int wm = wid >> 1;
    const int wn = wid & 1;
    const int gq = lane >> 2;
    const int tg = lane & 3;

    const int bb = blockIdx.y;
    const int n0 = blockIdx.x * 128;

    const float* Ap   = PHASE ? g_w2p : g_w1p;
    const float* bias = PHASE ? g_b2f : g_b1f;
    float*       out  = PHASE ? g_enh : g_fe;
    const float* xb   = xin   + (size_t)bb * Cc * HWc;
    const float* aggb = g_agg + (size_t)bb * Cc * HWc;

    uint32_t sAa, sBa;
    asm("{ .reg .u64 t; cvta.to.shared.u64 t, %1; cvt.u32.u64 %0, t; }" : "=r"(sAa) : "l"(sA));
    asm("{ .reg .u64 t; cvta.to.shared.u64 t, %1; cvt.u32.u64 %0, t; }" : "=r"(sBa) : "l"(sB));

    auto fill = [&](int ci) {
        const int buf = ci & (NSTG - 1);
        const int k0 = ci * BK;
        const uint32_t sAb = sAa + buf * (ABUF * 4);
        const uint32_t sBb = sBa + buf * (BBUF * 4);
#pragma unroll
        for (int it = 0; it < 4; it++) {
            int id = it * 256 + tid;
            const float* gp = &Ap[(size_t)ci * 4096 + id * 4];
            asm volatile("cp.async.cg.shared.global [%0], [%1], 16;"
                         :: "r"(sAb + (uint32_t)id * 16), "l"(gp));
        }
#pragma unroll
        for (int it = 0; it < 2; it++) {
            int id = it * 256 + tid;
            int kr = id >> 5, q = id & 31;
            int kg = k0 + kr;
            const float* brow;
            if (PHASE == 0) brow = xb + (size_t)kg * HWc;
            else            brow = (kg < Cc) ? xb + (size_t)kg * HWc
                                             : aggb + (size_t)(kg - Cc) * HWc;
            const float* gp = &brow[n0 + q * 4];
            uint32_t s = sBb + (uint32_t)(kr * PADB + q * 4) * 4;
            asm volatile("cp.async.cg.shared.global [%0], [%1], 16;" :: "r"(s), "l"(gp));
        }
        asm volatile("cp.async.commit_group;" ::: "memory");
    };

    float acc[4][8][4];
#pragma unroll
    for (int mt = 0; mt < 4; mt++)
#pragma unroll
        for (int nt = 0; nt < 8; nt++)
#pragma unroll
            for (int i = 0; i < 4; i++) acc[mt][nt][i] = 0.f;

    constexpr int NC = CIN / BK;
    fill(0); fill(1); fill(2);

    for (int ci = 0; ci < NC; ci++) {
        const int rem = NC - 1 - ci;
        if (rem >= 2)      asm volatile("cp.async.wait_group 2;" ::: "memory");
        else if (rem == 1) asm volatile("cp.async.wait_group 1;" ::: "memory");
        else               asm volatile("cp.async.wait_group 0;" ::: "memory");
        __syncthreads();
        if (ci + 3 < NC) fill(ci + 3);

        const int buf = ci & (NSTG - 1);
        const float* A_ = sA + buf * ABUF;
        const float* B_ = sB + buf * BBUF;
#pragma unroll
        for (int k8 = 0; k8 < 2; k8++) {
            const int kb = k8 * 8;
            uint32_t afr[4][4];
#pragma unroll
            for (int mt = 0; mt < 4; mt++) {
                int tile = wm * 4 + mt;
                const float4 v = *(const float4*)&A_[(tile * 2 + k8) * 128 + lane * 4];
                afr[mt][0] = __float_as_uint(v.x);
                afr[mt][1] = __float_as_uint(v.y);
                afr[mt][2] = __float_as_uint(v.z);
                afr[mt][3] = __float_as_uint(v.w);
            }
            uint32_t bfr[8][2];
#pragma unroll
            for (int nt = 0; nt < 8; nt++) {
                int col = wn * 64 + nt * 8 + gq;
                bfr[nt][0] = __float_as_uint(B_[(kb + tg) * PADB + col]);
                bfr[nt][1] = __float_as_uint(B_[(kb + 4 + tg) * PADB + col]);
            }
#pragma unroll
            for (int mt = 0; mt < 4; mt++)
#pragma unroll
                for (int nt = 0; nt < 8; nt++)
                    mma_tf32(acc[mt][nt], afr[mt], bfr[nt]);
        }
    }
    __syncthreads();

    // ---------------- epilogue: bias + relu + store + fused reduction ----------
    float ssq[8][2];
    float prt[4][2];
    if (PHASE == 0) {
#pragma unroll
        for (int nt = 0; nt < 8; nt++) { ssq[nt][0] = 0.f; ssq[nt][1] = 0.f; }
    } else {
#pragma unroll
        for (int mt = 0; mt < 4; mt++) { prt[mt][0] = 0.f; prt[mt][1] = 0.f; }
    }

#pragma unroll
    for (int mt = 0; mt < 4; mt++) {
        int row0 = wm * 64 + mt * 16 + gq;
        float bs0 = bias[row0];
        float bs1 = bias[row0 + 8];
        float* o0 = out + ((size_t)bb * Cc + row0) * HWc + n0;
        float* o1 = o0 + 8 * HWc;
#pragma unroll
        for (int nt = 0; nt < 8; nt++) {
            int col = wn * 64 + nt * 8 + 2 * tg;
            float v0x = fmaxf(acc[mt][nt][0] + bs0, 0.f);
            float v0y = fmaxf(acc[mt][nt][1] + bs0, 0.f);
            float v1x = fmaxf(acc[mt][nt][2] + bs1, 0.f);
            float v1y = fmaxf(acc[mt][nt][3] + bs1, 0.f);
            float2 a = {v0x, v0y}, b2 = {v1x, v1y};
            *(float2*)&o0[col] = a;
            *(float2*)&o1[col] = b2;
            if (PHASE == 0) {
                ssq[nt][0] += v0x * v0x + v1x * v1x;
                ssq[nt][1] += v0y * v0y + v1y * v1y;
            } else {
                prt[mt][0] += v0x + v0y;
                prt[mt][1] += v1x + v1y;
            }
        }
    }

    if (PHASE == 0) {
#pragma unroll
        for (int nt = 0; nt < 8; nt++) {
#pragma unroll
            for (int off = 16; off >= 4; off >>= 1) {
                ssq[nt][0] += __shfl_down_sync(0xffffffffu, ssq[nt][0], off);
                ssq[nt][1] += __shfl_down_sync(0xffffffffu, ssq[nt][1], off);
            }
        }
        if (lane < 4) {
#pragma unroll
            for (int nt = 0; nt < 8; nt++) {
                int col = wn * 64 + nt * 8 + 2 * tg;
                sred[wm * 128 + col]     = ssq[nt][0];
                sred[wm * 128 + col + 1] = ssq[nt][1];
            }
        }
        __syncthreads();
        if (tid < 128) {
            float s = sred[tid] + sred[128 + tid] + sred[256 + tid] + sred[384 + tid];
            g_nrm[bb * HWc + n0 + tid] = sqrtf(s);
        }
    } else {
#pragma unroll
        for (int mt = 0; mt < 4; mt++) {
            prt[mt][0] += __shfl_down_sync(0xffffffffu, prt[mt][0], 2);
            prt[mt][0] += __shfl_down_sync(0xffffffffu, prt[mt][0], 1);
            prt[mt][1] += __shfl_down_sync(0xffffffffu, prt[mt][1], 2);
            prt[mt][1] += __shfl_down_sync(0xffffffffu, prt[mt][1], 1);
        }
        if (tg == 0) {
#pragma unroll
            for (int mt = 0; mt < 4; mt++) {
                int row0 = wm * 64 + mt * 16 + gq;
                sred[wn * 256 + row0]     = prt[mt][0];
                sred[wn * 256 + row0 + 8] = prt[mt][1];
            }
        }
        __syncthreads();
        if (tid < 256)
            g_poolp[((size_t)bb * 32 + blockIdx.x) * 256 + tid] =
                sred[tid] + sred[256 + tid];
    }
}

// ---------------- phase A: partial cosine dots (8-way channel split) ------------
#define TILE 16
#define HALO 18
#define NPIX (HALO * HALO)
#define CKC  16
#define SHSTR 20
__global__ __launch_bounds__(256) void simdot_kernel() {
    __shared__ float sh[NPIX * SHSTR];

    const int b  = blockIdx.z;
    const int sp = blockIdx.y;               // channel split: 32 channels
    const int t  = blockIdx.x;
    const int h0 = (t >> 2) * TILE;
    const int w0 = (t & 3) * TILE;
    const int lx = threadIdx.x & (TILE - 1);
    const int ly = threadIdx.x / TILE;
    const int pc = ly * HALO + lx;

    const float* feb = g_fe + (size_t)b * Cc * HWc;

    float4 dot4[9];
#pragma unroll
    for (int k = 0; k < 9; k++) dot4[k] = make_float4(0.f, 0.f, 0.f, 0.f);

    const int c0 = sp * 32;
    for (int cc = c0; cc < c0 + 32; cc += CKC) {
        for (int idx = threadIdx.x; idx < CKC * NPIX; idx += 256) {
            int c = idx / NPIX;
            int p = idx - c * NPIX;
            int hy = p / HALO, hx = p - hy * HALO;
            int gh = h0 + hy - 1, gw = w0 + hx - 1;
            float v = 0.f;
            if (gh >= 0 && gh < Hh && gw >= 0 && gw < Ww)
                v = feb[(size_t)(cc + c) * HWc + gh * Ww + gw];
            sh[p * SHSTR + c] = v;
        }
        __syncthreads();
#pragma unroll
        for (int c4 = 0; c4 < 4; c4++) {
            float4 ctr = *(const float4*)&sh[(pc + HALO + 1) * SHSTR + c4 * 4];
#pragma unroll
            for (int di = 0; di < 3; di++)
#pragma unroll
                for (int dj = 0; dj < 3; dj++) {
                    float4 nb = *(const float4*)&sh[(pc + di * HALO + dj) * SHSTR + c4 * 4];
                    int k = di * 3 + dj;
                    dot4[k].x += ctr.x * nb.x;
                    dot4[k].y += ctr.y * nb.y;
                    dot4[k].z += ctr.z * nb.z;
                    dot4[k].w += ctr.w * nb.w;
                }
        }
        __syncthreads();
    }

    const int hw = (h0 + ly) * Ww + w0 + lx;
#pragma unroll
    for (int k = 0; k < 9; k++)
        g_dotp[(((size_t)sp * Bq + b) * 9 + k) * HWc + hw] =
            dot4[k].x + dot4[k].y + dot4[k].z + dot4[k].w;
}

// ---------------- phase B: combine 8 partials, cosine + softmax -----------------
__global__ void simsoft_kernel() {
    const int idx = blockIdx.x * 256 + threadIdx.x;
    const int b = idx >> 12;
    const int hw = idx & 4095;
    const int h = hw >> 6, w = hw & 63;

    float s[9];
#pragma unroll
    for (int k = 0; k < 9; k++) {
        float d = 0.f;
#pragma unroll
        for (int sp = 0; sp < 8; sp++)
            d += g_dotp[(((size_t)sp * Bq + b) * 9 + k) * HWc + hw];
        s[k] = d;
    }
    float nc = g_nrm[b * HWc + hw];
#pragma unroll
    for (int k = 0; k < 9; k++) {
        int di = k / 3, dj = k - 3 * di;
        int nh = h + di - 1, nw = w + dj - 1;
        float np = (nh >= 0 && nh < Hh && nw >= 0 && nw < Ww)
                       ? g_nrm[b * HWc + nh * Ww + nw] : 0.f;
        s[k] = s[k] / (nc * np + 1e-7f);
    }
    float mx = s[0];
#pragma unroll
    for (int k = 1; k < 9; k++) mx = fmaxf(mx, s[k]);
    float sum = 0.f;
#pragma unroll
    for (int k = 0; k < 9; k++) { s[k] = expf(s[k] - mx); sum += s[k]; }
    float inv = 1.f / sum;
#pragma unroll
    for (int k = 0; k < 9; k++)
        g_simw[((size_t)b * 9 + k) * HWc + hw] = s[k] * inv;
}

// ---------------- phase C: weighted 3x3 aggregation (R9 version) ----------------
__global__ __launch_bounds__(256) void agg_kernel(const float* __restrict__ xin) {
    __shared__ float sh[NPIX * SHSTR];

    const int b  = blockIdx.z;
    const int cc = blockIdx.y * CKC;
    const int t  = blockIdx.x;
    const int h0 = (t >> 2) * TILE;
    const int w0 = (t & 3) * TILE;
    const int lx = threadIdx.x & (TILE - 1);
    const int ly = threadIdx.x / TILE;
    const int pc = ly * HALO + lx;

    const float* xb = xin + (size_t)b * Cc * HWc;

    for (int idx = threadIdx.x; idx < CKC * NPIX; idx += 256) {
        int c = idx / NPIX;
        int p = idx - c * NPIX;
        int hy = p / HALO, hx = p - hy * HALO;
        int gh = h0 + hy - 1, gw = w0 + hx - 1;
        float v = 0.f;
        if (gh >= 0 && gh < Hh && gw >= 0 && gw < Ww)
            v = xb[(size_t)(cc + c) * HWc + gh * Ww + gw];
        sh[p * SHSTR + c] = v;
    }
    __syncthreads();

    const int hw = (h0 + ly) * Ww + w0 + lx;
    float s[9];
#pragma unroll
    for (int k = 0; k < 9; k++)
        s[k] = g_simw[((size_t)b * 9 + k) * HWc + hw];

    float* aggb = g_agg + (size_t)b * Cc * HWc;
#pragma unroll
    for (int c4 = 0; c4 < 4; c4++) {
        float4 a = make_float4(0.f, 0.f, 0.f, 0.f);
#pragma unroll
        for (int di = 0; di < 3; di++)
#pragma unroll
            for (int dj = 0; dj < 3; dj++) {
                float4 nb = *(const float4*)&sh[(pc + di * HALO + dj) * SHSTR + c4 * 4];
                float wk = s[di * 3 + dj];
                a.x += wk * nb.x;
                a.y += wk * nb.y;
                a.z += wk * nb.z;
                a.w += wk * nb.w;
            }
        size_t base = (size_t)(cc + c4 * 4) * HWc + hw;
        aggb[base]           = a.x;
        aggb[base + HWc]     = a.y;
        aggb[base + 2 * HWc] = a.z;
        aggb[base + 3 * HWc] = a.w;
    }
}

// ---------------- pool of x ------------------------------------------------------
__global__ void poolx_kernel(const float* __restrict__ xin) {
    const int c = blockIdx.x;
    const int b = blockIdx.y;
    const int tid = threadIdx.x;
    const float* src = xin + ((size_t)b * Cc + c) * HWc;
    float s = 0.f;
#pragma unroll
    for (int i = tid * 4; i < HWc; i += 1024) {
        float4 v = *(const float4*)&src[i];
        s += v.x + v.y + v.z + v.w;
    }
#pragma unroll
    for (int o = 16; o > 0; o >>= 1) s += __shfl_down_sync(0xffffffffu, s, o);
    __shared__ float red[8];
    if ((tid & 31) == 0) red[tid >> 5] = s;
    __syncthreads();
    if (tid < 8) {
        float t = red[tid];
#pragma unroll
        for (int o = 4; o > 0; o >>= 1) t += __shfl_down_sync(0xffu, t, o);
        if (tid == 0) g_pool[b * 512 + c] = t * (1.f / HWc);
    }
}

// ---------------- SE gate (absorbs enh pool-partial combine) --------------------
__global__ void gate_kernel(const float* __restrict__ w1, const float* __restrict__ b1,
                            const float* __restrict__ w2, const float* __restrict__ b2) {
    const int b = blockIdx.x;
    const int tid = threadIdx.x;
    __shared__ float sp[512];
    __shared__ float shid[64];
    // x half (precomputed by poolx)
    sp[tid] = g_pool[b * 512 + tid];
    // enhanced half: combine the 32 per-CTA partials here
    float s0 = 0.f;
#pragma unroll 8
    for (int nb = 0; nb < 32; nb++)
        s0 += g_poolp[((size_t)b * 32 + nb) * 256 + tid];
    sp[256 + tid] = s0 * (1.f / HWc);
    __syncthreads();
    if (tid < 64) {
        float s = b1[tid];
        const float* wr = w1 + tid * 512;
#pragma unroll 8
        for (int c = 0; c < 512; c++) s += wr[c] * sp[c];
        shid[tid] = fmaxf(s, 0.f);
    }
    __syncthreads();
    float s = b2[tid];
    const float* wr = w2 + tid * 64;
#pragma unroll
    for (int j = 0; j < 64; j++) s += wr[j] * shid[j];
    g_gate[b * 256 + tid] = 1.f / (1.f + expf(-s));
}

// ---------------- residual + gated enhancement ----------------------------------
__global__ void final_kernel(const float* __restrict__ xin, float* __restrict__ out) {
    size_t e = ((size_t)blockIdx.x * blockDim.x + threadIdx.x) * 4;
    if (e >= TOTAL) return;
    int bc = (int)(e >> 12);
    float g = g_gate[bc];
    float4 xv = *(const float4*)&xin[e];
    float4 ev = *(const float4*)&g_enh[e];
    float4 o;
    o.x = xv.x + g * ev.x;
    o.y = xv.y + g * ev.y;
    o.z = xv.z + g * ev.z;
    o.w = xv.w + g * ev.w;
    *(float4*)&out[e] = o;
}

// ---------------- launch ----------------------------------------------------------
extern "C" void kernel_launch(void* const* d_in, const int* in_sizes, int n_in,
                              void* d_out, int out_size) {
    const float* x       = (const float*)d_in[0];
    const float* w_embed = (const float*)d_in[1];
    const float* b_embed = (const float*)d_in[2];
    const float* bn1_g   = (const float*)d_in[3];
    const float* bn1_b   = (const float*)d_in[4];
    const float* bn1_m   = (const float*)d_in[5];
    const float* bn1_v   = (const float*)d_in[6];
    const float* w_enh   = (const float*)d_in[7];
    const float* b_enh   = (const float*)d_in[8];
    const float* bn2_g   = (const float*)d_in[9];
    const float* bn2_b   = (const float*)d_in[10];
    const float* bn2_m   = (const float*)d_in[11];
    const float* bn2_v   = (const float*)d_in[12];
    const float* w_g1    = (const float*)d_in[13];
    const float* b_g1    = (const float*)d_in[14];
    const float* w_g2    = (const float*)d_in[15];
    const float* b_g2    = (const float*)d_in[16];
    float* out = (float*)d_out;

    static bool attr_done = false;
    if (!attr_done) {
        cudaFuncSetAttribute(mma_gemm<256, 0>, cudaFuncAttributeMaxDynamicSharedMemorySize, GSMEM);
        cudaFuncSetAttribute(mma_gemm<512, 1>, cudaFuncAttributeMaxDynamicSharedMemorySize, GSMEM);
        attr_done = true;
    }

    fold_kernel<<<256, 256>>>(w_embed, b_embed, bn1_g, bn1_b, bn1_m, bn1_v, 256, 0);
    fold_kernel<<<256, 256>>>(w_enh,   b_enh,   bn2_g, bn2_b, bn2_m, bn2_v, 512, 1);
    poolx_kernel<<<dim3(256, Bq), 256>>>(x);

    mma_gemm<256, 0><<<dim3(32, Bq), 256, GSMEM>>>(x);          // fe + norm (4th: profiled)
    simdot_kernel<<<dim3(16, 8, Bq), 256>>>();                  // 1024 CTAs, 32 ch each
    simsoft_kernel<<<(Bq * HWc) / 256, 256>>>();
    agg_kernel<<<dim3(16, Cc / CKC, Bq), 256>>>(x);
    mma_gemm<512, 1><<<dim3(32, Bq), 256, GSMEM>>>(x);          // enhanced + pool partials

    gate_kernel<<<Bq, 256>>>(w_g1, b_g1, w_g2, b_g2);
    final_kernel<<<(unsigned)(TOTAL / 4 / 256), 256>>>(x, out);
}

// round 13
// speedup vs baseline: 1.1948x; 1.0276x over previous
#include <cuda_runtime.h>
#include <cstdint>
#include <cstddef>

#define Bq   8
#define Cc   256
#define Hh   64
#define Ww   64
#define HWc  4096
#define TOTAL (8UL*256*4096)

// ---------------- scratch (device globals) ------------------------------------
__device__ float g_fe  [TOTAL];
__device__ float g_agg [TOTAL];
__device__ float g_enh [TOTAL];
__device__ float g_w1p [256*256];
__device__ float g_w2p [256*512];
__device__ float g_b1f [256];
__device__ float g_b2f [256];
__device__ float g_nrm [Bq*HWc];
__device__ float g_dotp[8*Bq*4*HWc];   // partial dots [split][b][4 dirs][hw]
__device__ float g_simw[Bq*9*HWc];
__device__ float g_poolp[Bq*32*256];
__device__ float g_pool[Bq*512];
__device__ float g_gate[Bq*256];

// ---------------- BN fold -> fragment-ready permuted layout --------------------
__global__ void fold_kernel(const float* __restrict__ w, const float* __restrict__ bsrc,
                            const float* __restrict__ gm, const float* __restrict__ bt,
                            const float* __restrict__ mn, const float* __restrict__ vr,
                            int cin, int which) {
    int o = blockIdx.x;
    float inv = gm[o] * rsqrtf(vr[o] + 1e-5f);
    float* wp = which ? g_w2p : g_w1p;
    float* bf = which ? g_b2f : g_b1f;
    const int tile = o >> 4;
    const int r = o & 15;
    const int gqv = r & 7;
    const int hi = r >> 3;
    for (int k = threadIdx.x; k < cin; k += blockDim.x) {
        int ci = k >> 4, kk = k & 15;
        int k8 = kk >> 3, kw = kk & 7;
        int lane = gqv * 4 + (kw & 3);
        int e = hi + ((kw >> 2) << 1);
        wp[(size_t)ci * 4096 + tile * 256 + k8 * 128 + lane * 4 + e] = inv * w[o * cin + k];
    }
    if (threadIdx.x == 0)
        bf[o] = bsrc[o] * inv + bt[o] - mn[o] * inv;
}

// ---------------- mma.sync tf32 GEMM (R9/R12 version) ---------------------------
#define BK   16
#define PADB 136
#define NSTG 4
#define ABUF 4096
#define BBUF (BK * PADB)
#define GSMEM (NSTG * (ABUF + BBUF) * 4)

__device__ __forceinline__ void mma_tf32(float c[4], const uint32_t a[4], const uint32_t b[2]) {
    asm volatile(
        "mma.sync.aligned.m16n8k8.row.col.f32.tf32.tf32.f32 "
        "{%0,%1,%2,%3}, {%4,%5,%6,%7}, {%8,%9}, {%0,%1,%2,%3};"
        : "+f"(c[0]), "+f"(c[1]), "+f"(c[2]), "+f"(c[3])
        : "r"(a[0]), "r"(a[1]), "r"(a[2]), "r"(a[3]), "r"(b[0]), "r"(b[1]));
}

template <int CIN, int PHASE>
__global__ __launch_bounds__(256) void mma_gemm(const float* __restrict__ xin) {
    extern __shared__ float dsm[];
    float* sA = dsm;
    float* sB = dsm + NSTG * ABUF;
    float* sred = sB;

    const int tid  = threadIdx.x;
    const int wid  = tid >> 5;
    const int lane = tid & 31;
    const int wm = wid >> 1;
    const int wn = wid & 1;
    const int gq = lane >> 2;
    const int tg = lane & 3;

    const int bb = blockIdx.y;
    const int n0 = blockIdx.x * 128;

    const float* Ap   = PHASE ? g_w2p : g_w1p;
    const float* bias = PHASE ? g_b2f : g_b1f;
    float*       out  = PHASE ? g_enh : g_fe;
    const float* xb   = xin   + (size_t)bb * Cc * HWc;
    const float* aggb = g_agg + (size_t)bb * Cc * HWc;

    uint32_t sAa, sBa;
    asm("{ .reg .u64 t; cvta.to.shared.u64 t, %1; cvt.u32.u64 %0, t; }" : "=r"(sAa) : "l"(sA));
    asm("{ .reg .u64 t; cvta.to.shared.u64 t, %1; cvt.u32.u64 %0, t; }" : "=r"(sBa) : "l"(sB));

    auto fill = [&](int ci) {
        const int buf = ci & (NSTG - 1);
        const int k0 = ci * BK;
        const uint32_t sAb = sAa + buf * (ABUF * 4);
        const uint32_t sBb = sBa + buf * (BBUF * 4);
#pragma unroll
        for (int it = 0; it < 4; it++) {
            int id = it * 256 + tid;
            const float* gp = &Ap[(size_t)ci * 4096 + id * 4];
            asm volatile("cp.async.cg.shared.global [%0], [%1], 16;"
                         :: "r"(sAb + (uint32_t)id * 16), "l"(gp));
        }
#pragma unroll
        for (int it = 0; it < 2; it++) {
            int id = it * 256 + tid;
            int kr = id >> 5, q = id & 31;
            int kg = k0 + kr;
            const float* brow;
            if (PHASE == 0) brow = xb + (size_t)kg * HWc;
            else            brow = (kg < Cc) ? xb + (size_t)kg * HWc
                                             : aggb + (size_t)(kg - Cc) * HWc;
            const float* gp = &brow[n0 + q * 4];
            uint32_t s = sBb + (uint32_t)(kr * PADB + q * 4) * 4;
            asm volatile("cp.async.cg.shared.global [%0], [%1], 16;" :: "r"(s), "l"(gp));
        }
        asm volatile("cp.async.commit_group;" ::: "memory");
    };

    float acc[4][8][4];
#pragma unroll
    for (int mt = 0; mt < 4; mt++)
#pragma unroll
        for (int nt = 0; nt < 8; nt++)
#pragma unroll
            for (int i = 0; i < 4; i++) acc[mt][nt][i] = 0.f;

    constexpr int NC = CIN / BK;
    fill(0); fill(1); fill(2);

    for (int ci = 0; ci < NC; ci++) {
        const int rem = NC - 1 - ci;
        if (rem >= 2)      asm volatile("cp.async.wait_group 2;" ::: "memory");
        else if (rem == 1) asm volatile("cp.async.wait_group 1;" ::: "memory");
        else               asm volatile("cp.async.wait_group 0;" ::: "memory");
        __syncthreads();
        if (ci + 3 < NC) fill(ci + 3);

        const int buf = ci & (NSTG - 1);
        const float* A_ = sA + buf * ABUF;
        const float* B_ = sB + buf * BBUF;
#pragma unroll
        for (int k8 = 0; k8 < 2; k8++) {
            const int kb = k8 * 8;
            uint32_t afr[4][4];
#pragma unroll
            for (int mt = 0; mt < 4; mt++) {
                int tile = wm * 4 + mt;
                const float4 v = *(const float4*)&A_[(tile * 2 + k8) * 128 + lane * 4];
                afr[mt][0] = __float_as_uint(v.x);
                afr[mt][1] = __float_as_uint(v.y);
                afr[mt][2] = __float_as_uint(v.z);
                afr[mt][3] = __float_as_uint(v.w);
            }
            uint32_t bfr[8][2];
#pragma unroll
            for (int nt = 0; nt < 8; nt++) {
                int col = wn * 64 + nt * 8 + gq;
                bfr[nt][0] = __float_as_uint(B_[(kb + tg) * PADB + col]);
                bfr[nt][1] = __float_as_uint(B_[(kb + 4 + tg) * PADB + col]);
            }
#pragma unroll
            for (int mt = 0; mt < 4; mt++)
#pragma unroll
                for (int nt = 0; nt < 8; nt++)
                    mma_tf32(acc[mt][nt], afr[mt], bfr[nt]);
        }
    }
    __syncthreads();

    // ---------------- epilogue -----------------------------------------------------
    float ssq[8][2];
    float prt[4][2];
    if (PHASE == 0) {
#pragma unroll
        for (int nt = 0; nt < 8; nt++) { ssq[nt][0] = 0.f; ssq[nt][1] = 0.f; }
    } else {
#pragma unroll
        for (int mt = 0; mt < 4; mt++) { prt[mt][0] = 0.f; prt[mt][1] = 0.f; }
    }

#pragma unroll
    for (int mt = 0; mt < 4; mt++) {
        int row0 = wm * 64 + mt * 16 + gq;
        float bs0 = bias[row0];
        float bs1 = bias[row0 + 8];
        float* o0 = out + ((size_t)bb * Cc + row0) * HWc + n0;
        float* o1 = o0 + 8 * HWc;
#pragma unroll
        for (int nt = 0; nt < 8; nt++) {
            int col = wn * 64 + nt * 8 + 2 * tg;
            float v0x = fmaxf(acc[mt][nt][0] + bs0, 0.f);
            float v0y = fmaxf(acc[mt][nt][1] + bs0, 0.f);
            float v1x = fmaxf(acc[mt][nt][2] + bs1, 0.f);
            float v1y = fmaxf(acc[mt][nt][3] + bs1, 0.f);
            float2 a = {v0x, v0y}, b2 = {v1x, v1y};
            *(float2*)&o0[col] = a;
            *(float2*)&o1[col] = b2;
            if (PHASE == 0) {
                ssq[nt][0] += v0x * v0x + v1x * v1x;
                ssq[nt][1] += v0y * v0y + v1y * v1y;
            } else {
                prt[mt][0] += v0x + v0y;
                prt[mt][1] += v1x + v1y;
            }
        }
    }

    if (PHASE == 0) {
#pragma unroll
        for (int nt = 0; nt < 8; nt++) {
#pragma unroll
            for (int off = 16; off >= 4; off >>= 1) {
                ssq[nt][0] += __shfl_down_sync(0xffffffffu, ssq[nt][0], off);
                ssq[nt][1] += __shfl_down_sync(0xffffffffu, ssq[nt][1], off);
            }
        }
        if (lane < 4) {
#pragma unroll
            for (int nt = 0; nt < 8; nt++) {
                int col = wn * 64 + nt * 8 + 2 * tg;
                sred[wm * 128 + col]     = ssq[nt][0];
                sred[wm * 128 + col + 1] = ssq[nt][1];
            }
        }
        __syncthreads();
        if (tid < 128) {
            float s = sred[tid] + sred[128 + tid] + sred[256 + tid] + sred[384 + tid];
            g_nrm[bb * HWc + n0 + tid] = sqrtf(s);
        }
    } else {
#pragma unroll
        for (int mt = 0; mt < 4; mt++) {
            prt[mt][0] += __shfl_down_sync(0xffffffffu, prt[mt][0], 2);
            prt[mt][0] += __shfl_down_sync(0xffffffffu, prt[mt][0], 1);
            prt[mt][1] += __shfl_down_sync(0xffffffffu, prt[mt][1], 2);
            prt[mt][1] += __shfl_down_sync(0xffffffffu, prt[mt][1], 1);
        }
        if (tg == 0) {
#pragma unroll
            for (int mt = 0; mt < 4; mt++) {
                int row0 = wm * 64 + mt * 16 + gq;
                sred[wn * 256 + row0]     = prt[mt][0];
                sred[wn * 256 + row0 + 8] = prt[mt][1];
            }
        }
        __syncthreads();
        if (tid < 256)
            g_poolp[((size_t)bb * 32 + blockIdx.x) * 256 + tid] =
                sred[tid] + sred[256 + tid];
    }
}

// ---------------- phase A: 4-direction partial dots (symmetry-halved) -----------
// dirs k=0..3 = window offsets (-1,-1),(-1,0),(-1,1),(0,-1); mirrors derived in simsoft.
#define TILE 16
#define HALO 18
#define NPIX (HALO * HALO)
#define CKC  16
#define SHSTR 20
__global__ __launch_bounds__(256) void simdot_kernel() {
    __shared__ float sh[NPIX * SHSTR];

    const int b  = blockIdx.z;
    const int sp = blockIdx.y;               // channel split: 32 channels
    const int t  = blockIdx.x;
    const int h0 = (t >> 2) * TILE;
    const int w0 = (t & 3) * TILE;
    const int lx = threadIdx.x & (TILE - 1);
    const int ly = threadIdx.x / TILE;
    const int pc = ly * HALO + lx;

    const float* feb = g_fe + (size_t)b * Cc * HWc;

    float4 dot4[4];
#pragma unroll
    for (int k = 0; k < 4; k++) dot4[k] = make_float4(0.f, 0.f, 0.f, 0.f);

    const int c0 = sp * 32;
    for (int cc = c0; cc < c0 + 32; cc += CKC) {
        for (int idx = threadIdx.x; idx < CKC * NPIX; idx += 256) {
            int c = idx / NPIX;
            int p = idx - c * NPIX;
            int hy = p / HALO, hx = p - hy * HALO;
            int gh = h0 + hy - 1, gw = w0 + hx - 1;
            float v = 0.f;
            if (gh >= 0 && gh < Hh && gw >= 0 && gw < Ww)
                v = feb[(size_t)(cc + c) * HWc + gh * Ww + gw];
            sh[p * SHSTR + c] = v;
        }
        __syncthreads();
#pragma unroll
        for (int c4 = 0; c4 < 4; c4++) {
            float4 ctr = *(const float4*)&sh[(pc + HALO + 1) * SHSTR + c4 * 4];
            // neighbors for dirs (-1,-1),(-1,0),(-1,1),(0,-1): halo idx pc+0, pc+1, pc+2, pc+HALO
            const int nbo[4] = { pc, pc + 1, pc + 2, pc + HALO };
#pragma unroll
            for (int k = 0; k < 4; k++) {
                float4 nb = *(const float4*)&sh[nbo[k] * SHSTR + c4 * 4];
                dot4[k].x += ctr.x * nb.x;
                dot4[k].y += ctr.y * nb.y;
                dot4[k].z += ctr.z * nb.z;
                dot4[k].w += ctr.w * nb.w;
            }
        }
        __syncthreads();
    }

    const int hw = (h0 + ly) * Ww + w0 + lx;
#pragma unroll
    for (int k = 0; k < 4; k++)
        g_dotp[(((size_t)sp * Bq + b) * 4 + k) * HWc + hw] =
            dot4[k].x + dot4[k].y + dot4[k].z + dot4[k].w;
}

// ---------------- phase B: reconstruct 9 sims, cosine + softmax -----------------
__global__ void simsoft_kernel() {
    const int idx = blockIdx.x * 256 + threadIdx.x;
    const int b = idx >> 12;
    const int hw = idx & 4095;
    const int h = hw >> 6, w = hw & 63;

    float nc = g_nrm[b * HWc + hw];
    float s[9];

    // k = 0..3: direct dirs (-1,-1),(-1,0),(-1,1),(0,-1)
    const int dh0[4] = {-1, -1, -1, 0};
    const int dw0[4] = {-1,  0,  1, -1};
#pragma unroll
    for (int k = 0; k < 4; k++) {
        float d = 0.f;
#pragma unroll
        for (int sp = 0; sp < 8; sp++)
            d += g_dotp[(((size_t)sp * Bq + b) * 4 + k) * HWc + hw];
        int nh = h + dh0[k], nw = w + dw0[k];
        float np = (nh >= 0 && nh < Hh && nw >= 0 && nw < Ww)
                       ? g_nrm[b * HWc + nh * Ww + nw] : 0.f;
        s[k] = d / (nc * np + 1e-7f);
    }
    // k = 4: center, dot = nc^2
    s[4] = (nc * nc) / (nc * nc + 1e-7f);
    // k = 5..8: mirrors of m = 8-k at pixel p + dir_k
#pragma unroll
    for (int k = 5; k < 9; k++) {
        int m = 8 - k;
        int nh = h - dh0[m], nw = w - dw0[m];   // dir_k = -dir_m
        if (nh >= 0 && nh < Hh && nw >= 0 && nw < Ww) {
            int q = nh * Ww + nw;
            float d = 0.f;
#pragma unroll
            for (int sp = 0; sp < 8; sp++)
                d += g_dotp[(((size_t)sp * Bq + b) * 4 + m) * HWc + q];
            float np = g_nrm[b * HWc + q];
            s[k] = d / (nc * np + 1e-7f);
        } else {
            s[k] = 0.f;
        }
    }

    float mx = s[0];
#pragma unroll
    for (int k = 1; k < 9; k++) mx = fmaxf(mx, s[k]);
    float sum = 0.f;
#pragma unroll
    for (int k = 0; k < 9; k++) { s[k] = expf(s[k] - mx); sum += s[k]; }
    float inv = 1.f / sum;
#pragma unroll
    for (int k = 0; k < 9; k++)
        g_simw[((size_t)b * 9 + k) * HWc + hw] = s[k] * inv;
}

// ---------------- phase C: weighted 3x3 aggregation ------------------------------
__global__ __launch_bounds__(256) void agg_kernel(const float* __restrict__ xin) {
    __shared__ float sh[NPIX * SHSTR];

    const int b  = blockIdx.z;
    const int cc = blockIdx.y * CKC;
    const int t  = blockIdx.x;
    const int h0 = (t >> 2) * TILE;
    const int w0 = (t & 3) * TILE;
    const int lx = threadIdx.x & (TILE - 1);
    const int ly = threadIdx.x / TILE;
    const int pc = ly * HALO + lx;

    const float* xb = xin + (size_t)b * Cc * HWc;

    for (int idx = threadIdx.x; idx < CKC * NPIX; idx += 256) {
        int c = idx / NPIX;
        int p = idx - c * NPIX;
        int hy = p / HALO, hx = p - hy * HALO;
        int gh = h0 + hy - 1, gw = w0 + hx - 1;
        float v = 0.f;
        if (gh >= 0 && gh < Hh && gw >= 0 && gw < Ww)
            v = xb[(size_t)(cc + c) * HWc + gh * Ww + gw];
        sh[p * SHSTR + c] = v;
    }
    __syncthreads();

    const int hw = (h0 + ly) * Ww + w0 + lx;
    float s[9];
#pragma unroll
    for (int k = 0; k < 9; k++)
        s[k] = g_simw[((size_t)b * 9 + k) * HWc + hw];

    float* aggb = g_agg + (size_t)b * Cc * HWc;
#pragma unroll
    for (int c4 = 0; c4 < 4; c4++) {
        float4 a = make_float4(0.f, 0.f, 0.f, 0.f);
#pragma unroll
        for (int di = 0; di < 3; di++)
#pragma unroll
            for (int dj = 0; dj < 3; dj++) {
                float4 nb = *(const float4*)&sh[(pc + di * HALO + dj) * SHSTR + c4 * 4];
                float wk = s[di * 3 + dj];
                a.x += wk * nb.x;
                a.y += wk * nb.y;
                a.z += wk * nb.z;
                a.w += wk * nb.w;
            }
        size_t base = (size_t)(cc + c4 * 4) * HWc + hw;
        aggb[base]           = a.x;
        aggb[base + HWc]     = a.y;
        aggb[base + 2 * HWc] = a.z;
        aggb[base + 3 * HWc] = a.w;
    }
}

// ---------------- pool of x ------------------------------------------------------
__global__ void poolx_kernel(const float* __restrict__ xin) {
    const int c = blockIdx.x;
    const int b = blockIdx.y;
    const int tid = threadIdx.x;
    const float* src = xin + ((size_t)b * Cc + c) * HWc;
    float s = 0.f;
#pragma unroll
    for (int i = tid * 4; i < HWc; i += 1024) {
        float4 v = *(const float4*)&src[i];
        s += v.x + v.y + v.z + v.w;
    }
#pragma unroll
    for (int o = 16; o > 0; o >>= 1) s += __shfl_down_sync(0xffffffffu, s, o);
    __shared__ float red[8];
    if ((tid & 31) == 0) red[tid >> 5] = s;
    __syncthreads();
    if (tid < 8) {
        float t = red[tid];
#pragma unroll
        for (int o = 4; o > 0; o >>= 1) t += __shfl_down_sync(0xffu, t, o);
        if (tid == 0) g_pool[b * 512 + c] = t * (1.f / HWc);
    }
}

// ---------------- SE gate (absorbs enh pool-partial combine) --------------------
__global__ void gate_kernel(const float* __restrict__ w1, const float* __restrict__ b1,
                            const float* __restrict__ w2, const float* __restrict__ b2) {
    const int b = blockIdx.x;
    const int tid = threadIdx.x;
    __shared__ float sp[512];
    __shared__ float shid[64];
    sp[tid] = g_pool[b * 512 + tid];
    float s0 = 0.f;
#pragma unroll 8
    for (int nb = 0; nb < 32; nb++)
        s0 += g_poolp[((size_t)b * 32 + nb) * 256 + tid];
    sp[256 + tid] = s0 * (1.f / HWc);
    __syncthreads();
    if (tid < 64) {
        float s = b1[tid];
        const float* wr = w1 + tid * 512;
#pragma unroll 8
        for (int c = 0; c < 512; c++) s += wr[c] * sp[c];
        shid[tid] = fmaxf(s, 0.f);
    }
    __syncthreads();
    float s = b2[tid];
    const float* wr = w2 + tid * 64;
#pragma unroll
    for (int j = 0; j < 64; j++) s += wr[j] * shid[j];
    g_gate[b * 256 + tid] = 1.f / (1.f + expf(-s));
}

// ---------------- residual + gated enhancement ----------------------------------
__global__ void final_kernel(const float* __restrict__ xin, float* __restrict__ out) {
    size_t e = ((size_t)blockIdx.x * blockDim.x + threadIdx.x) * 4;
    if (e >= TOTAL) return;
    int bc = (int)(e >> 12);
    float g = g_gate[bc];
    float4 xv = *(const float4*)&xin[e];
    float4 ev = *(const float4*)&g_enh[e];
    float4 o;
    o.x = xv.x + g * ev.x;
    o.y = xv.y + g * ev.y;
    o.z = xv.z + g * ev.z;
    o.w = xv.w + g * ev.w;
    *(float4*)&out[e] = o;
}

// ---------------- launch ----------------------------------------------------------
extern "C" void kernel_launch(void* const* d_in, const int* in_sizes, int n_in,
                              void* d_out, int out_size) {
    const float* x       = (const float*)d_in[0];
    const float* w_embed = (const float*)d_in[1];
    const float* b_embed = (const float*)d_in[2];
    const float* bn1_g   = (const float*)d_in[3];
    const float* bn1_b   = (const float*)d_in[4];
    const float* bn1_m   = (const float*)d_in[5];
    const float* bn1_v   = (const float*)d_in[6];
    const float* w_enh   = (const float*)d_in[7];
    const float* b_enh   = (const float*)d_in[8];
    const float* bn2_g   = (const float*)d_in[9];
    const float* bn2_b   = (const float*)d_in[10];
    const float* bn2_m   = (const float*)d_in[11];
    const float* bn2_v   = (const float*)d_in[12];
    const float* w_g1    = (const float*)d_in[13];
    const float* b_g1    = (const float*)d_in[14];
    const float* w_g2    = (const float*)d_in[15];
    const float* b_g2    = (const float*)d_in[16];
    float* out = (float*)d_out;

    static bool attr_done = false;
    if (!attr_done) {
        cudaFuncSetAttribute(mma_gemm<256, 0>, cudaFuncAttributeMaxDynamicSharedMemorySize, GSMEM);
        cudaFuncSetAttribute(mma_gemm<512, 1>, cudaFuncAttributeMaxDynamicSharedMemorySize, GSMEM);
        attr_done = true;
    }

    fold_kernel<<<256, 256>>>(w_embed, b_embed, bn1_g, bn1_b, bn1_m, bn1_v, 256, 0);
    fold_kernel<<<256, 256>>>(w_enh,   b_enh,   bn2_g, bn2_b, bn2_m, bn2_v, 512, 1);
    poolx_kernel<<<dim3(256, Bq), 256>>>(x);

    mma_gemm<256, 0><<<dim3(32, Bq), 256, GSMEM>>>(x);          // fe + norm
    simdot_kernel<<<dim3(16, 8, Bq), 256>>>();                  // 4-dir partial dots
    simsoft_kernel<<<(Bq * HWc) / 256, 256>>>();
    agg_kernel<<<dim3(16, Cc / CKC, Bq), 256>>>(x);
    mma_gemm<512, 1><<<dim3(32, Bq), 256, GSMEM>>>(x);          // enhanced + pool partials

    gate_kernel<<<Bq, 256>>>(w_g1, b_g1, w_g2, b_g2);
    final_kernel<<<(unsigned)(TOTAL / 4 / 256), 256>>>(x, out);
}

// round 14
// speedup vs baseline: 1.2223x; 1.0230x over previous
#include <cuda_runtime.h>
#include <cstdint>
#include <cstddef>

#define Bq   8
#define Cc   256
#define Hh   64
#define Ww   64
#define HWc  4096
#define TOTAL (8UL*256*4096)

// ---------------- scratch (device globals) ------------------------------------
__device__ float g_fe  [TOTAL];
__device__ float g_agg [TOTAL];
__device__ float g_enh [TOTAL];
__device__ float g_w1p [256*256];
__device__ float g_w2p [256*512];
__device__ float g_b1f [256];
__device__ float g_b2f [256];
__device__ float g_nrm [Bq*HWc];
__device__ float g_dotp[8*Bq*4*HWc];   // partial dots [split][b][4 dirs][hw]
__device__ float g_simw[Bq*9*HWc];
__device__ float g_poolp[Bq*32*256];   // enh pool partials per n-block
__device__ float g_pxp [Bq*16*256];    // x pool partials per tile (fused in agg)
__device__ float g_gate[Bq*256];

// ---------------- BN fold -> fragment-ready permuted layout --------------------
__global__ void fold_kernel(const float* __restrict__ w, const float* __restrict__ bsrc,
                            const float* __restrict__ gm, const float* __restrict__ bt,
                            const float* __restrict__ mn, const float* __restrict__ vr,
                            int cin, int which) {
    int o = blockIdx.x;
    float inv = gm[o] * rsqrtf(vr[o] + 1e-5f);
    float* wp = which ? g_w2p : g_w1p;
    float* bf = which ? g_b2f : g_b1f;
    const int tile = o >> 4;
    const int r = o & 15;
    const int gqv = r & 7;
    const int hi = r >> 3;
    for (int k = threadIdx.x; k < cin; k += blockDim.x) {
        int ci = k >> 4, kk = k & 15;
        int k8 = kk >> 3, kw = kk & 7;
        int lane = gqv * 4 + (kw & 3);
        int e = hi + ((kw >> 2) << 1);
        wp[(size_t)ci * 4096 + tile * 256 + k8 * 128 + lane * 4 + e] = inv * w[o * cin + k];
    }
    if (threadIdx.x == 0)
        bf[o] = bsrc[o] * inv + bt[o] - mn[o] * inv;
}

// ---------------- mma.sync tf32 GEMM (R9/R13 version, unchanged) ----------------
#define BK   16
#define PADB 136
#define NSTG 4
#define ABUF 4096
#define BBUF (BK * PADB)
#define GSMEM (NSTG * (ABUF + BBUF) * 4)

__device__ __forceinline__ void mma_tf32(float c[4], const uint32_t a[4], const uint32_t b[2]) {
    asm volatile(
        "mma.sync.aligned.m16n8k8.row.col.f32.tf32.tf32.f32 "
        "{%0,%1,%2,%3}, {%4,%5,%6,%7}, {%8,%9}, {%0,%1,%2,%3};"
        : "+f"(c[0]), "+f"(c[1]), "+f"(c[2]), "+f"(c[3])
        : "r"(a[0]), "r"(a[1]), "r"(a[2]), "r"(a[3]), "r"(b[0]), "r"(b[1]));
}

template <int CIN, int PHASE>
__global__ __launch_bounds__(256) void mma_gemm(const float* __restrict__ xin) {
    extern __shared__ float dsm[];
    float* sA = dsm;
    float* sB = dsm + NSTG * ABUF;
    float* sred = sB;

    const int tid  = threadIdx.x;
    const int wid  = tid >> 5;
    const int lane = tid & 31;
    const int wm = wid >> 1;
    const int wn = wid & 1;
    const int gq = lane >> 2;
    const int tg = lane & 3;

    const int bb = blockIdx.y;
    const int n0 = blockIdx.x * 128;

    const float* Ap   = PHASE ? g_w2p : g_w1p;
    const float* bias = PHASE ? g_b2f : g_b1f;
    float*       out  = PHASE ? g_enh : g_fe;
    const float* xb   = xin   + (size_t)bb * Cc * HWc;
    const float* aggb = g_agg + (size_t)bb * Cc * HWc;

    uint32_t sAa, sBa;
    asm("{ .reg .u64 t; cvta.to.shared.u64 t, %1; cvt.u32.u64 %0, t; }" : "=r"(sAa) : "l"(sA));
    asm("{ .reg .u64 t; cvta.to.shared.u64 t, %1; cvt.u32.u64 %0, t; }" : "=r"(sBa) : "l"(sB));

    auto fill = [&](int ci) {
        const int buf = ci & (NSTG - 1);
        const int k0 = ci * BK;
        const uint32_t sAb = sAa + buf * (ABUF * 4);
        const uint32_t sBb = sBa + buf * (BBUF * 4);
#pragma unroll
        for (int it = 0; it < 4; it++) {
            int id = it * 256 + tid;
            const float* gp = &Ap[(size_t)ci * 4096 + id * 4];
            asm volatile("cp.async.cg.shared.global [%0], [%1], 16;"
                         :: "r"(sAb + (uint32_t)id * 16), "l"(gp));
        }
#pragma unroll
        for (int it = 0; it < 2; it++) {
            int id = it * 256 + tid;
            int kr = id >> 5, q = id & 31;
            int kg = k0 + kr;
            const float* brow;
            if (PHASE == 0) brow = xb + (size_t)kg * HWc;
            else            brow = (kg < Cc) ? xb + (size_t)kg * HWc
                                             : aggb + (size_t)(kg - Cc) * HWc;
            const float* gp = &brow[n0 + q * 4];
            uint32_t s = sBb + (uint32_t)(kr * PADB + q * 4) * 4;
            asm volatile("cp.async.cg.shared.global [%0], [%1], 16;" :: "r"(s), "l"(gp));
        }
        asm volatile("cp.async.commit_group;" ::: "memory");
    };

    float acc[4][8][4];
#pragma unroll
    for (int mt = 0; mt < 4; mt++)
#pragma unroll
        for (int nt = 0; nt < 8; nt++)
#pragma unroll
            for (int i = 0; i < 4; i++) acc[mt][nt][i] = 0.f;

    constexpr int NC = CIN / BK;
    fill(0); fill(1); fill(2);

    for (int ci = 0; ci < NC; ci++) {
        const int rem = NC - 1 - ci;
        if (rem >= 2)      asm volatile("cp.async.wait_group 2;" ::: "memory");
        else if (rem == 1) asm volatile("cp.async.wait_group 1;" ::: "memory");
        else               asm volatile("cp.async.wait_group 0;" ::: "memory");
        __syncthreads();
        if (ci + 3 < NC) fill(ci + 3);

        const int buf = ci & (NSTG - 1);
        const float* A_ = sA + buf * ABUF;
        const float* B_ = sB + buf * BBUF;
#pragma unroll
        for (int k8 = 0; k8 < 2; k8++) {
            const int kb = k8 * 8;
            uint32_t afr[4][4];
#pragma unroll
            for (int mt = 0; mt < 4; mt++) {
                int tile = wm * 4 + mt;
                const float4 v = *(const float4*)&A_[(tile * 2 + k8) * 128 + lane * 4];
                afr[mt][0] = __float_as_uint(v.x);
                afr[mt][1] = __float_as_uint(v.y);
                afr[mt][2] = __float_as_uint(v.z);
                afr[mt][3] = __float_as_uint(v.w);
            }
            uint32_t bfr[8][2];
#pragma unroll
            for (int nt = 0; nt < 8; nt++) {
                int col = wn * 64 + nt * 8 + gq;
                bfr[nt][0] = __float_as_uint(B_[(kb + tg) * PADB + col]);
                bfr[nt][1] = __float_as_uint(B_[(kb + 4 + tg) * PADB + col]);
            }
#pragma unroll
            for (int mt = 0; mt < 4; mt++)
#pragma unroll
                for (int nt = 0; nt < 8; nt++)
                    mma_tf32(acc[mt][nt], afr[mt], bfr[nt]);
        }
    }
    __syncthreads();

    float ssq[8][2];
    float prt[4][2];
    if (PHASE == 0) {
#pragma unroll
        for (int nt = 0; nt < 8; nt++) { ssq[nt][0] = 0.f; ssq[nt][1] = 0.f; }
    } else {
#pragma unroll
        for (int mt = 0; mt < 4; mt++) { prt[mt][0] = 0.f; prt[mt][1] = 0.f; }
    }

#pragma unroll
    for (int mt = 0; mt < 4; mt++) {
        int row0 = wm * 64 + mt * 16 + gq;
        float bs0 = bias[row0];
        float bs1 = bias[row0 + 8];
        float* o0 = out + ((size_t)bb * Cc + row0) * HWc + n0;
        float* o1 = o0 + 8 * HWc;
#pragma unroll
        for (int nt = 0; nt < 8; nt++) {
            int col = wn * 64 + nt * 8 + 2 * tg;
            float v0x = fmaxf(acc[mt][nt][0] + bs0, 0.f);
            float v0y = fmaxf(acc[mt][nt][1] + bs0, 0.f);
            float v1x = fmaxf(acc[mt][nt][2] + bs1, 0.f);
            float v1y = fmaxf(acc[mt][nt][3] + bs1, 0.f);
            float2 a = {v0x, v0y}, b2 = {v1x, v1y};
            *(float2*)&o0[col] = a;
            *(float2*)&o1[col] = b2;
            if (PHASE == 0) {
                ssq[nt][0] += v0x * v0x + v1x * v1x;
                ssq[nt][1] += v0y * v0y + v1y * v1y;
            } else {
                prt[mt][0] += v0x + v0y;
                prt[mt][1] += v1x + v1y;
            }
        }
    }

    if (PHASE == 0) {
#pragma unroll
        for (int nt = 0; nt < 8; nt++) {
#pragma unroll
            for (int off = 16; off >= 4; off >>= 1) {
                ssq[nt][0] += __shfl_down_sync(0xffffffffu, ssq[nt][0], off);
                ssq[nt][1] += __shfl_down_sync(0xffffffffu, ssq[nt][1], off);
            }
        }
        if (lane < 4) {
#pragma unroll
            for (int nt = 0; nt < 8; nt++) {
                int col = wn * 64 + nt * 8 + 2 * tg;
                sred[wm * 128 + col]     = ssq[nt][0];
                sred[wm * 128 + col + 1] = ssq[nt][1];
            }
        }
        __syncthreads();
        if (tid < 128) {
            float s = sred[tid] + sred[128 + tid] + sred[256 + tid] + sred[384 + tid];
            g_nrm[bb * HWc + n0 + tid] = sqrtf(s);
        }
    } else {
#pragma unroll
        for (int mt = 0; mt < 4; mt++) {
            prt[mt][0] += __shfl_down_sync(0xffffffffu, prt[mt][0], 2);
            prt[mt][0] += __shfl_down_sync(0xffffffffu, prt[mt][0], 1);
            prt[mt][1] += __shfl_down_sync(0xffffffffu, prt[mt][1], 2);
            prt[mt][1] += __shfl_down_sync(0xffffffffu, prt[mt][1], 1);
        }
        if (tg == 0) {
#pragma unroll
            for (int mt = 0; mt < 4; mt++) {
                int row0 = wm * 64 + mt * 16 + gq;
                sred[wn * 256 + row0]     = prt[mt][0];
                sred[wn * 256 + row0 + 8] = prt[mt][1];
            }
        }
        __syncthreads();
        if (tid < 256)
            g_poolp[((size_t)bb * 32 + blockIdx.x) * 256 + tid] =
                sred[tid] + sred[256 + tid];
    }
}

// ---------------- phase A: 4-dir partial dots, CKC=32 single chunk ---------------
#define TILE 16
#define HALO 18
#define NPIX (HALO * HALO)
#define SDSTR 36              // 32 ch + 4 pad; /4 = 9 odd -> conflict-free float4
__global__ __launch_bounds__(256) void simdot_kernel() {
    __shared__ float sh[NPIX * SDSTR];   // 46656 B

    const int b  = blockIdx.z;
    const int sp = blockIdx.y;           // 32 channels per split
    const int t  = blockIdx.x;
    const int h0 = (t >> 2) * TILE;
    const int w0 = (t & 3) * TILE;
    const int lx = threadIdx.x & (TILE - 1);
    const int ly = threadIdx.x / TILE;
    const int pc = ly * HALO + lx;

    const float* feb = g_fe + (size_t)b * Cc * HWc + (size_t)(sp * 32) * HWc;

    for (int idx = threadIdx.x; idx < 32 * NPIX; idx += 256) {
        int c = idx / NPIX;
        int p = idx - c * NPIX;
        int hy = p / HALO, hx = p - hy * HALO;
        int gh = h0 + hy - 1, gw = w0 + hx - 1;
        float v = 0.f;
        if (gh >= 0 && gh < Hh && gw >= 0 && gw < Ww)
            v = feb[(size_t)c * HWc + gh * Ww + gw];
        sh[p * SDSTR + c] = v;
    }
    __syncthreads();

    float4 dot4[4];
#pragma unroll
    for (int k = 0; k < 4; k++) dot4[k] = make_float4(0.f, 0.f, 0.f, 0.f);

#pragma unroll
    for (int c4 = 0; c4 < 8; c4++) {
        float4 ctr = *(const float4*)&sh[(pc + HALO + 1) * SDSTR + c4 * 4];
        const int nbo[4] = { pc, pc + 1, pc + 2, pc + HALO };
#pragma unroll
        for (int k = 0; k < 4; k++) {
            float4 nb = *(const float4*)&sh[nbo[k] * SDSTR + c4 * 4];
            dot4[k].x += ctr.x * nb.x;
            dot4[k].y += ctr.y * nb.y;
            dot4[k].z += ctr.z * nb.z;
            dot4[k].w += ctr.w * nb.w;
        }
    }

    const int hw = (h0 + ly) * Ww + w0 + lx;
#pragma unroll
    for (int k = 0; k < 4; k++)
        g_dotp[(((size_t)sp * Bq + b) * 4 + k) * HWc + hw] =
            dot4[k].x + dot4[k].y + dot4[k].z + dot4[k].w;
}

// ---------------- phase B: reconstruct 9 sims, cosine + softmax ------------------
__global__ void simsoft_kernel() {
    const int idx = blockIdx.x * 256 + threadIdx.x;
    const int b = idx >> 12;
    const int hw = idx & 4095;
    const int h = hw >> 6, w = hw & 63;

    float nc = g_nrm[b * HWc + hw];
    float s[9];

    const int dh0[4] = {-1, -1, -1, 0};
    const int dw0[4] = {-1,  0,  1, -1};
#pragma unroll
    for (int k = 0; k < 4; k++) {
        float d = 0.f;
#pragma unroll
        for (int sp = 0; sp < 8; sp++)
            d += g_dotp[(((size_t)sp * Bq + b) * 4 + k) * HWc + hw];
        int nh = h + dh0[k], nw = w + dw0[k];
        float np = (nh >= 0 && nh < Hh && nw >= 0 && nw < Ww)
                       ? g_nrm[b * HWc + nh * Ww + nw] : 0.f;
        s[k] = d / (nc * np + 1e-7f);
    }
    s[4] = (nc * nc) / (nc * nc + 1e-7f);
#pragma unroll
    for (int k = 5; k < 9; k++) {
        int m = 8 - k;
        int nh = h - dh0[m], nw = w - dw0[m];
        if (nh >= 0 && nh < Hh && nw >= 0 && nw < Ww) {
            int q = nh * Ww + nw;
            float d = 0.f;
#pragma unroll
            for (int sp = 0; sp < 8; sp++)
                d += g_dotp[(((size_t)sp * Bq + b) * 4 + m) * HWc + q];
            float np = g_nrm[b * HWc + q];
            s[k] = d / (nc * np + 1e-7f);
        } else {
            s[k] = 0.f;
        }
    }

    float mx = s[0];
#pragma unroll
    for (int k = 1; k < 9; k++) mx = fmaxf(mx, s[k]);
    float sum = 0.f;
#pragma unroll
    for (int k = 0; k < 9; k++) { s[k] = expf(s[k] - mx); sum += s[k]; }
    float inv = 1.f / sum;
#pragma unroll
    for (int k = 0; k < 9; k++)
        g_simw[((size_t)b * 9 + k) * HWc + hw] = s[k] * inv;
}

// ---------------- phase C: weighted 3x3 aggregation + fused pool-of-x ------------
#define CKC  16
#define SHSTR 20
__global__ __launch_bounds__(256) void agg_kernel(const float* __restrict__ xin) {
    __shared__ float sh[NPIX * SHSTR];
    __shared__ float pred[256];

    const int b  = blockIdx.z;
    const int cc = blockIdx.y * CKC;
    const int t  = blockIdx.x;
    const int h0 = (t >> 2) * TILE;
    const int w0 = (t & 3) * TILE;
    const int lx = threadIdx.x & (TILE - 1);
    const int ly = threadIdx.x / TILE;
    const int pc = ly * HALO + lx;
    const int tid = threadIdx.x;

    const float* xb = xin + (size_t)b * Cc * HWc;

    for (int idx = tid; idx < CKC * NPIX; idx += 256) {
        int c = idx / NPIX;
        int p = idx - c * NPIX;
        int hy = p / HALO, hx = p - hy * HALO;
        int gh = h0 + hy - 1, gw = w0 + hx - 1;
        float v = 0.f;
        if (gh >= 0 && gh < Hh && gw >= 0 && gw < Ww)
            v = xb[(size_t)(cc + c) * HWc + gh * Ww + gw];
        sh[p * SHSTR + c] = v;
    }
    __syncthreads();

    const int hw = (h0 + ly) * Ww + w0 + lx;
    float s[9];
#pragma unroll
    for (int k = 0; k < 9; k++)
        s[k] = g_simw[((size_t)b * 9 + k) * HWc + hw];

    float* aggb = g_agg + (size_t)b * Cc * HWc;
#pragma unroll
    for (int c4 = 0; c4 < 4; c4++) {
        float4 a = make_float4(0.f, 0.f, 0.f, 0.f);
#pragma unroll
        for (int di = 0; di < 3; di++)
#pragma unroll
            for (int dj = 0; dj < 3; dj++) {
                float4 nb = *(const float4*)&sh[(pc + di * HALO + dj) * SHSTR + c4 * 4];
                float wk = s[di * 3 + dj];
                a.x += wk * nb.x;
                a.y += wk * nb.y;
                a.z += wk * nb.z;
                a.w += wk * nb.w;
            }
        size_t base = (size_t)(cc + c4 * 4) * HWc + hw;
        aggb[base]           = a.x;
        aggb[base + HWc]     = a.y;
        aggb[base + 2 * HWc] = a.z;
        aggb[base + 3 * HWc] = a.w;
    }

    // ---- fused pool-of-x partial: sum inner 16x16 pixels for this CTA's 16 ch
    {
        const int cl = tid & 15;            // channel 0..15
        const int pg = tid >> 4;            // pixel row 0..15
        float sum = 0.f;
#pragma unroll
        for (int i = 0; i < 16; i++)
            sum += sh[((pg + 1) * HALO + i + 1) * SHSTR + cl];
        pred[pg * 16 + cl] = sum;
    }
    __syncthreads();
    if (tid < 16) {
        float sum = 0.f;
#pragma unroll
        for (int g = 0; g < 16; g++) sum += pred[g * 16 + tid];
        g_pxp[((size_t)b * 16 + t) * 256 + cc + tid] = sum;
    }
}

// ---------------- SE gate (combines x + enh pool partials) -----------------------
__global__ void gate_kernel(const float* __restrict__ w1, const float* __restrict__ b1,
                            const float* __restrict__ w2, const float* __restrict__ b2) {
    const int b = blockIdx.x;
    const int tid = threadIdx.x;
    __shared__ float sp[512];
    __shared__ float shid[64];
    float sx = 0.f;
#pragma unroll
    for (int t = 0; t < 16; t++)
        sx += g_pxp[((size_t)b * 16 + t) * 256 + tid];
    sp[tid] = sx * (1.f / HWc);
    float s0 = 0.f;
#pragma unroll 8
    for (int nb = 0; nb < 32; nb++)
        s0 += g_poolp[((size_t)b * 32 + nb) * 256 + tid];
    sp[256 + tid] = s0 * (1.f / HWc);
    __syncthreads();
    if (tid < 64) {
        float s = b1[tid];
        const float* wr = w1 + tid * 512;
#pragma unroll 8
        for (int c = 0; c < 512; c++) s += wr[c] * sp[c];
        shid[tid] = fmaxf(s, 0.f);
    }
    __syncthreads();
    float s = b2[tid];
    const float* wr = w2 + tid * 64;
#pragma unroll
    for (int j = 0; j < 64; j++) s += wr[j] * shid[j];
    g_gate[b * 256 + tid] = 1.f / (1.f + expf(-s));
}

// ---------------- residual + gated enhancement -----------------------------------
__global__ void final_kernel(const float* __restrict__ xin, float* __restrict__ out) {
    size_t e = ((size_t)blockIdx.x * blockDim.x + threadIdx.x) * 4;
    if (e >= TOTAL) return;
    int bc = (int)(e >> 12);
    float g = g_gate[bc];
    float4 xv = *(const float4*)&xin[e];
    float4 ev = *(const float4*)&g_enh[e];
    float4 o;
    o.x = xv.x + g * ev.x;
    o.y = xv.y + g * ev.y;
    o.z = xv.z + g * ev.z;
    o.w = xv.w + g * ev.w;
    *(float4*)&out[e] = o;
}

// ---------------- launch -----------------------------------------------------------
extern "C" void kernel_launch(void* const* d_in, const int* in_sizes, int n_in,
                              void* d_out, int out_size) {
    const float* x       = (const float*)d_in[0];
    const float* w_embed = (const float*)d_in[1];
    const float* b_embed = (const float*)d_in[2];
    const float* bn1_g   = (const float*)d_in[3];
    const float* bn1_b   = (const float*)d_in[4];
    const float* bn1_m   = (const float*)d_in[5];
    const float* bn1_v   = (const float*)d_in[6];
    const float* w_enh   = (const float*)d_in[7];
    const float* b_enh   = (const float*)d_in[8];
    const float* bn2_g   = (const float*)d_in[9];
    const float* bn2_b   = (const float*)d_in[10];
    const float* bn2_m   = (const float*)d_in[11];
    const float* bn2_v   = (const float*)d_in[12];
    const float* w_g1    = (const float*)d_in[13];
    const float* b_g1    = (const float*)d_in[14];
    const float* w_g2    = (const float*)d_in[15];
    const float* b_g2    = (const float*)d_in[16];
    float* out = (float*)d_out;

    static bool attr_done = false;
    if (!attr_done) {
        cudaFuncSetAttribute(mma_gemm<256, 0>, cudaFuncAttributeMaxDynamicSharedMemorySize, GSMEM);
        cudaFuncSetAttribute(mma_gemm<512, 1>, cudaFuncAttributeMaxDynamicSharedMemorySize, GSMEM);
        attr_done = true;
    }

    fold_kernel<<<256, 256>>>(w_embed, b_embed, bn1_g, bn1_b, bn1_m, bn1_v, 256, 0);
    fold_kernel<<<256, 256>>>(w_enh,   b_enh,   bn2_g, bn2_b, bn2_m, bn2_v, 512, 1);

    mma_gemm<256, 0><<<dim3(32, Bq), 256, GSMEM>>>(x);          // fe + norm
    simdot_kernel<<<dim3(16, 8, Bq), 256>>>();                  // 4th: profiled
    simsoft_kernel<<<(Bq * HWc) / 256, 256>>>();
    agg_kernel<<<dim3(16, Cc / CKC, Bq), 256>>>(x);             // + fused pool-of-x
    mma_gemm<512, 1><<<dim3(32, Bq), 256, GSMEM>>>(x);          // enhanced + pool partials

    gate_kernel<<<Bq, 256>>>(w_g1, b_g1, w_g2, b_g2);
    final_kernel<<<(unsigned)(TOTAL / 4 / 256), 256>>>(x, out);
}

// round 15
// speedup vs baseline: 1.2466x; 1.0199x over previous
#include <cuda_runtime.h>
#include <cstdint>
#include <cstddef>

#define Bq   8
#define Cc   256
#define Hh   64
#define Ww   64
#define HWc  4096
#define TOTAL (8UL*256*4096)

// ---------------- scratch (device globals) ------------------------------------
__device__ float g_fe  [TOTAL];
__device__ float g_agg [TOTAL];
__device__ float g_enh [TOTAL];
__device__ float g_w1p [256*256];
__device__ float g_w2p [256*512];
__device__ float g_b1f [256];
__device__ float g_b2f [256];
__device__ float g_nrm [Bq*HWc];
__device__ float g_dotp[8*Bq*4*HWc];
__device__ float g_simw[Bq*9*HWc];
__device__ float g_poolp[Bq*32*256];
__device__ float g_pxp [Bq*16*256];
__device__ float g_gate[Bq*256];

// ---------------- BN fold (both weights in one launch) --------------------------
__global__ void fold_kernel(const float* __restrict__ w1, const float* __restrict__ b1s,
                            const float* __restrict__ g1, const float* __restrict__ t1,
                            const float* __restrict__ m1, const float* __restrict__ v1,
                            const float* __restrict__ w2, const float* __restrict__ b2s,
                            const float* __restrict__ g2, const float* __restrict__ t2,
                            const float* __restrict__ m2, const float* __restrict__ v2) {
    const int which = blockIdx.x >> 8;
    const int o = blockIdx.x & 255;
    const int cin = which ? 512 : 256;
    const float* w   = which ? w2  : w1;
    const float* bs  = which ? b2s : b1s;
    const float* gm  = which ? g2  : g1;
    const float* bt  = which ? t2  : t1;
    const float* mn  = which ? m2  : m1;
    const float* vr  = which ? v2  : v1;
    float inv = gm[o] * rsqrtf(vr[o] + 1e-5f);
    float* wp = which ? g_w2p : g_w1p;
    float* bf = which ? g_b2f : g_b1f;
    const int tile = o >> 4;
    const int r = o & 15;
    const int gqv = r & 7;
    const int hi = r >> 3;
    for (int k = threadIdx.x; k < cin; k += blockDim.x) {
        int ci = k >> 4, kk = k & 15;
        int k8 = kk >> 3, kw = kk & 7;
        int lane = gqv * 4 + (kw & 3);
        int e = hi + ((kw >> 2) << 1);
        wp[(size_t)ci * 4096 + tile * 256 + k8 * 128 + lane * 4 + e] = inv * w[o * cin + k];
    }
    if (threadIdx.x == 0)
        bf[o] = bs[o] * inv + bt[o] - mn[o] * inv;
}

// ---------------- mma.sync tf32 GEMM (unchanged) --------------------------------
#define BK   16
#define PADB 136
#define NSTG 4
#define ABUF 4096
#define BBUF (BK * PADB)
#define GSMEM (NSTG * (ABUF + BBUF) * 4)

__device__ __forceinline__ void mma_tf32(float c[4], const uint32_t a[4], const uint32_t b[2]) {
    asm volatile(
        "mma.sync.aligned.m16n8k8.row.col.f32.tf32.tf32.f32 "
        "{%0,%1,%2,%3}, {%4,%5,%6,%7}, {%8,%9}, {%0,%1,%2,%3};"
        : "+f"(c[0]), "+f"(c[1]), "+f"(c[2]), "+f"(c[3])
        : "r"(a[0]), "r"(a[1]), "r"(a[2]), "r"(a[3]), "r"(b[0]), "r"(b[1]));
}

template <int CIN, int PHASE>
__global__ __launch_bounds__(256) void mma_gemm(const float* __restrict__ xin) {
    extern __shared__ float dsm[];
    float* sA = dsm;
    float* sB = dsm + NSTG * ABUF;
    float* sred = sB;

    const int tid  = threadIdx.x;
    const int wid  = tid >> 5;
    const int lane = tid & 31;
    const int wm = wid >> 1;
    const int wn = wid & 1;
    const int gq = lane >> 2;
    const int tg = lane & 3;

    const int bb = blockIdx.y;
    const int n0 = blockIdx.x * 128;

    const float* Ap   = PHASE ? g_w2p : g_w1p;
    const float* bias = PHASE ? g_b2f : g_b1f;
    float*       out  = PHASE ? g_enh : g_fe;
    const float* xb   = xin   + (size_t)bb * Cc * HWc;
    const float* aggb = g_agg + (size_t)bb * Cc * HWc;

    uint32_t sAa, sBa;
    asm("{ .reg .u64 t; cvta.to.shared.u64 t, %1; cvt.u32.u64 %0, t; }" : "=r"(sAa) : "l"(sA));
    asm("{ .reg .u64 t; cvta.to.shared.u64 t, %1; cvt.u32.u64 %0, t; }" : "=r"(sBa) : "l"(sB));

    auto fill = [&](int ci) {
        const int buf = ci & (NSTG - 1);
        const int k0 = ci * BK;
        const uint32_t sAb = sAa + buf * (ABUF * 4);
        const uint32_t sBb = sBa + buf * (BBUF * 4);
#pragma unroll
        for (int it = 0; it < 4; it++) {
            int id = it * 256 + tid;
            const float* gp = &Ap[(size_t)ci * 4096 + id * 4];
            asm volatile("cp.async.cg.shared.global [%0], [%1], 16;"
                         :: "r"(sAb + (uint32_t)id * 16), "l"(gp));
        }
#pragma unroll
        for (int it = 0; it < 2; it++) {
            int id = it * 256 + tid;
            int kr = id >> 5, q = id & 31;
            int kg = k0 + kr;
            const float* brow;
            if (PHASE == 0) brow = xb + (size_t)kg * HWc;
            else            brow = (kg < Cc) ? xb + (size_t)kg * HWc
                                             : aggb + (size_t)(kg - Cc) * HWc;
            const float* gp = &brow[n0 + q * 4];
            uint32_t s = sBb + (uint32_t)(kr * PADB + q * 4) * 4;
            asm volatile("cp.async.cg.shared.global [%0], [%1], 16;" :: "r"(s), "l"(gp));
        }
        asm volatile("cp.async.commit_group;" ::: "memory");
    };

    float acc[4][8][4];
#pragma unroll
    for (int mt = 0; mt < 4; mt++)
#pragma unroll
        for (int nt = 0; nt < 8; nt++)
#pragma unroll
            for (int i = 0; i < 4; i++) acc[mt][nt][i] = 0.f;

    constexpr int NC = CIN / BK;
    fill(0); fill(1); fill(2);

    for (int ci = 0; ci < NC; ci++) {
        const int rem = NC - 1 - ci;
        if (rem >= 2)      asm volatile("cp.async.wait_group 2;" ::: "memory");
        else if (rem == 1) asm volatile("cp.async.wait_group 1;" ::: "memory");
        else               asm volatile("cp.async.wait_group 0;" ::: "memory");
        __syncthreads();
        if (ci + 3 < NC) fill(ci + 3);

        const int buf = ci & (NSTG - 1);
        const float* A_ = sA + buf * ABUF;
        const float* B_ = sB + buf * BBUF;
#pragma unroll
        for (int k8 = 0; k8 < 2; k8++) {
            const int kb = k8 * 8;
            uint32_t afr[4][4];
#pragma unroll
            for (int mt = 0; mt < 4; mt++) {
                int tile = wm * 4 + mt;
                const float4 v = *(const float4*)&A_[(tile * 2 + k8) * 128 + lane * 4];
                afr[mt][0] = __float_as_uint(v.x);
                afr[mt][1] = __float_as_uint(v.y);
                afr[mt][2] = __float_as_uint(v.z);
                afr[mt][3] = __float_as_uint(v.w);
            }
            uint32_t bfr[8][2];
#pragma unroll
            for (int nt = 0; nt < 8; nt++) {
                int col = wn * 64 + nt * 8 + gq;
                bfr[nt][0] = __float_as_uint(B_[(kb + tg) * PADB + col]);
                bfr[nt][1] = __float_as_uint(B_[(kb + 4 + tg) * PADB + col]);
            }
#pragma unroll
            for (int mt = 0; mt < 4; mt++)
#pragma unroll
                for (int nt = 0; nt < 8; nt++)
                    mma_tf32(acc[mt][nt], afr[mt], bfr[nt]);
        }
    }
    __syncthreads();

    float ssq[8][2];
    float prt[4][2];
    if (PHASE == 0) {
#pragma unroll
        for (int nt = 0; nt < 8; nt++) { ssq[nt][0] = 0.f; ssq[nt][1] = 0.f; }
    } else {
#pragma unroll
        for (int mt = 0; mt < 4; mt++) { prt[mt][0] = 0.f; prt[mt][1] = 0.f; }
    }

#pragma unroll
    for (int mt = 0; mt < 4; mt++) {
        int row0 = wm * 64 + mt * 16 + gq;
        float bs0 = bias[row0];
        float bs1 = bias[row0 + 8];
        float* o0 = out + ((size_t)bb * Cc + row0) * HWc + n0;
        float* o1 = o0 + 8 * HWc;
#pragma unroll
        for (int nt = 0; nt < 8; nt++) {
            int col = wn * 64 + nt * 8 + 2 * tg;
            float v0x = fmaxf(acc[mt][nt][0] + bs0, 0.f);
            float v0y = fmaxf(acc[mt][nt][1] + bs0, 0.f);
            float v1x = fmaxf(acc[mt][nt][2] + bs1, 0.f);
            float v1y = fmaxf(acc[mt][nt][3] + bs1, 0.f);
            float2 a = {v0x, v0y}, b2 = {v1x, v1y};
            *(float2*)&o0[col] = a;
            *(float2*)&o1[col] = b2;
            if (PHASE == 0) {
                ssq[nt][0] += v0x * v0x + v1x * v1x;
                ssq[nt][1] += v0y * v0y + v1y * v1y;
            } else {
                prt[mt][0] += v0x + v0y;
                prt[mt][1] += v1x + v1y;
            }
        }
    }

    if (PHASE == 0) {
#pragma unroll
        for (int nt = 0; nt < 8; nt++) {
#pragma unroll
            for (int off = 16; off >= 4; off >>= 1) {
                ssq[nt][0] += __shfl_down_sync(0xffffffffu, ssq[nt][0], off);
                ssq[nt][1] += __shfl_down_sync(0xffffffffu, ssq[nt][1], off);
            }
        }
        if (lane < 4) {
#pragma unroll
            for (int nt = 0; nt < 8; nt++) {
                int col = wn * 64 + nt * 8 + 2 * tg;
                sred[wm * 128 + col]     = ssq[nt][0];
                sred[wm * 128 + col + 1] = ssq[nt][1];
            }
        }
        __syncthreads();
        if (tid < 128) {
            float s = sred[tid] + sred[128 + tid] + sred[256 + tid] + sred[384 + tid];
            g_nrm[bb * HWc + n0 + tid] = sqrtf(s);
        }
    } else {
#pragma unroll
        for (int mt = 0; mt < 4; mt++) {
            prt[mt][0] += __shfl_down_sync(0xffffffffu, prt[mt][0], 2);
            prt[mt][0] += __shfl_down_sync(0xffffffffu, prt[mt][0], 1);
            prt[mt][1] += __shfl_down_sync(0xffffffffu, prt[mt][1], 2);
            prt[mt][1] += __shfl_down_sync(0xffffffffu, prt[mt][1], 1);
        }
        if (tg == 0) {
#pragma unroll
            for (int mt = 0; mt < 4; mt++) {
                int row0 = wm * 64 + mt * 16 + gq;
                sred[wn * 256 + row0]     = prt[mt][0];
                sred[wn * 256 + row0 + 8] = prt[mt][1];
            }
        }
        __syncthreads();
        if (tid < 256)
            g_poolp[((size_t)bb * 32 + blockIdx.x) * 256 + tid] =
                sred[tid] + sred[256 + tid];
    }
}

// ---------------- phase A: 4-dir partial dots (div-free fill) --------------------
#define TILE 16
#define HALO 18
#define NPIX (HALO * HALO)
#define SDSTR 36
__global__ __launch_bounds__(256) void simdot_kernel() {
    __shared__ float sh[NPIX * SDSTR];

    const int b  = blockIdx.z;
    const int sp = blockIdx.y;
    const int t  = blockIdx.x;
    const int h0 = (t >> 2) * TILE;
    const int w0 = (t & 3) * TILE;
    const int lx = threadIdx.x & (TILE - 1);
    const int ly = threadIdx.x / TILE;
    const int pc = ly * HALO + lx;

    const float* feb = g_fe + (size_t)b * Cc * HWc + (size_t)(sp * 32) * HWc;

    // div-free fill: running (c, hy, hx); step 256 = +14 rows, +4 cols (carry<=1)
    {
        int hy = threadIdx.x / HALO;
        int hx = threadIdx.x - hy * HALO;
        int c = 0;
        for (int idx = threadIdx.x; idx < 32 * NPIX; idx += 256) {
            int gh = h0 + hy - 1, gw = w0 + hx - 1;
            float v = 0.f;
            if (gh >= 0 && gh < Hh && gw >= 0 && gw < Ww)
                v = feb[(size_t)c * HWc + gh * Ww + gw];
            sh[(hy * HALO + hx) * SDSTR + c] = v;
            hy += 14; hx += 4;
            if (hx >= HALO) { hx -= HALO; hy++; }
            if (hy >= HALO) { hy -= HALO; c++; }
        }
    }
    __syncthreads();

    float4 dot4[4];
#pragma unroll
    for (int k = 0; k < 4; k++) dot4[k] = make_float4(0.f, 0.f, 0.f, 0.f);

#pragma unroll
    for (int c4 = 0; c4 < 8; c4++) {
        float4 ctr = *(const float4*)&sh[(pc + HALO + 1) * SDSTR + c4 * 4];
        const int nbo[4] = { pc, pc + 1, pc + 2, pc + HALO };
#pragma unroll
        for (int k = 0; k < 4; k++) {
            float4 nb = *(const float4*)&sh[nbo[k] * SDSTR + c4 * 4];
            dot4[k].x += ctr.x * nb.x;
            dot4[k].y += ctr.y * nb.y;
            dot4[k].z += ctr.z * nb.z;
            dot4[k].w += ctr.w * nb.w;
        }
    }

    const int hw = (h0 + ly) * Ww + w0 + lx;
#pragma unroll
    for (int k = 0; k < 4; k++)
        g_dotp[(((size_t)sp * Bq + b) * 4 + k) * HWc + hw] =
            dot4[k].x + dot4[k].y + dot4[k].z + dot4[k].w;
}

// ---------------- phase B: reconstruct 9 sims, cosine + softmax ------------------
__global__ void simsoft_kernel() {
    const int idx = blockIdx.x * 256 + threadIdx.x;
    const int b = idx >> 12;
    const int hw = idx & 4095;
    const int h = hw >> 6, w = hw & 63;

    float nc = g_nrm[b * HWc + hw];
    float s[9];

    const int dh0[4] = {-1, -1, -1, 0};
    const int dw0[4] = {-1,  0,  1, -1};
#pragma unroll
    for (int k = 0; k < 4; k++) {
        float d = 0.f;
#pragma unroll
        for (int sp = 0; sp < 8; sp++)
            d += g_dotp[(((size_t)sp * Bq + b) * 4 + k) * HWc + hw];
        int nh = h + dh0[k], nw = w + dw0[k];
        float np = (nh >= 0 && nh < Hh && nw >= 0 && nw < Ww)
                       ? g_nrm[b * HWc + nh * Ww + nw] : 0.f;
        s[k] = d / (nc * np + 1e-7f);
    }
    s[4] = (nc * nc) / (nc * nc + 1e-7f);
#pragma unroll
    for (int k = 5; k < 9; k++) {
        int m = 8 - k;
        int nh = h - dh0[m], nw = w - dw0[m];
        if (nh >= 0 && nh < Hh && nw >= 0 && nw < Ww) {
            int q = nh * Ww + nw;
            float d = 0.f;
#pragma unroll
            for (int sp = 0; sp < 8; sp++)
                d += g_dotp[(((size_t)sp * Bq + b) * 4 + m) * HWc + q];
            float np = g_nrm[b * HWc + q];
            s[k] = d / (nc * np + 1e-7f);
        } else {
            s[k] = 0.f;
        }
    }

    float mx = s[0];
#pragma unroll
    for (int k = 1; k < 9; k++) mx = fmaxf(mx, s[k]);
    float sum = 0.f;
#pragma unroll
    for (int k = 0; k < 9; k++) { s[k] = expf(s[k] - mx); sum += s[k]; }
    float inv = 1.f / sum;
#pragma unroll
    for (int k = 0; k < 9; k++)
        g_simw[((size_t)b * 9 + k) * HWc + hw] = s[k] * inv;
}

// ---------------- phase C: 3x3 aggregation + fused pool-of-x (div-free fill) -----
#define CKC  16
#define SHSTR 20
__global__ __launch_bounds__(256) void agg_kernel(const float* __restrict__ xin) {
    __shared__ float sh[NPIX * SHSTR];
    __shared__ float pred[256];

    const int b  = blockIdx.z;
    const int cc = blockIdx.y * CKC;
    const int t  = blockIdx.x;
    const int h0 = (t >> 2) * TILE;
    const int w0 = (t & 3) * TILE;
    const int lx = threadIdx.x & (TILE - 1);
    const int ly = threadIdx.x / TILE;
    const int pc = ly * HALO + lx;
    const int tid = threadIdx.x;

    const float* xb = xin + (size_t)b * Cc * HWc + (size_t)cc * HWc;

    {
        int hy = tid / HALO;
        int hx = tid - hy * HALO;
        int c = 0;
        for (int idx = tid; idx < CKC * NPIX; idx += 256) {
            int gh = h0 + hy - 1, gw = w0 + hx - 1;
            float v = 0.f;
            if (gh >= 0 && gh < Hh && gw >= 0 && gw < Ww)
                v = xb[(size_t)c * HWc + gh * Ww + gw];
            sh[(hy * HALO + hx) * SHSTR + c] = v;
            hy += 14; hx += 4;
            if (hx >= HALO) { hx -= HALO; hy++; }
            if (hy >= HALO) { hy -= HALO; c++; }
        }
    }
    __syncthreads();

    const int hw = (h0 + ly) * Ww + w0 + lx;
    float s[9];
#pragma unroll
    for (int k = 0; k < 9; k++)
        s[k] = g_simw[((size_t)b * 9 + k) * HWc + hw];

    float* aggb = g_agg + (size_t)b * Cc * HWc;
#pragma unroll
    for (int c4 = 0; c4 < 4; c4++) {
        float4 a = make_float4(0.f, 0.f, 0.f, 0.f);
#pragma unroll
        for (int di = 0; di < 3; di++)
#pragma unroll
            for (int dj = 0; dj < 3; dj++) {
                float4 nb = *(const float4*)&sh[(pc + di * HALO + dj) * SHSTR + c4 * 4];
                float wk = s[di * 3 + dj];
                a.x += wk * nb.x;
                a.y += wk * nb.y;
                a.z += wk * nb.z;
                a.w += wk * nb.w;
            }
        size_t base = (size_t)(cc + c4 * 4) * HWc + hw;
        aggb[base]           = a.x;
        aggb[base + HWc]     = a.y;
        aggb[base + 2 * HWc] = a.z;
        aggb[base + 3 * HWc] = a.w;
    }

    {
        const int cl = tid & 15;
        const int pg = tid >> 4;
        float sum = 0.f;
#pragma unroll
        for (int i = 0; i < 16; i++)
            sum += sh[((pg + 1) * HALO + i + 1) * SHSTR + cl];
        pred[pg * 16 + cl] = sum;
    }
    __syncthreads();
    if (tid < 16) {
        float sum = 0.f;
#pragma unroll
        for (int g = 0; g < 16; g++) sum += pred[g * 16 + tid];
        g_pxp[((size_t)b * 16 + t) * 256 + cc + tid] = sum;
    }
}

// ---------------- SE gate ---------------------------------------------------------
__global__ void gate_kernel(const float* __restrict__ w1, const float* __restrict__ b1,
                            const float* __restrict__ w2, const float* __restrict__ b2) {
    const int b = blockIdx.x;
    const int tid = threadIdx.x;
    __shared__ float sp[512];
    __shared__ float shid[64];
    float sx = 0.f;
#pragma unroll
    for (int t = 0; t < 16; t++)
        sx += g_pxp[((size_t)b * 16 + t) * 256 + tid];
    sp[tid] = sx * (1.f / HWc);
    float s0 = 0.f;
#pragma unroll 8
    for (int nb = 0; nb < 32; nb++)
        s0 += g_poolp[((size_t)b * 32 + nb) * 256 + tid];
    sp[256 + tid] = s0 * (1.f / HWc);
    __syncthreads();
    if (tid < 64) {
        float s = b1[tid];
        const float* wr = w1 + tid * 512;
#pragma unroll 8
        for (int c = 0; c < 512; c++) s += wr[c] * sp[c];
        shid[tid] = fmaxf(s, 0.f);
    }
    __syncthreads();
    float s = b2[tid];
    const float* wr = w2 + tid * 64;
#pragma unroll
    for (int j = 0; j < 64; j++) s += wr[j] * shid[j];
    g_gate[b * 256 + tid] = 1.f / (1.f + expf(-s));
}

// ---------------- residual + gated enhancement -------------------------------------
__global__ void final_kernel(const float* __restrict__ xin, float* __restrict__ out) {
    size_t e = ((size_t)blockIdx.x * blockDim.x + threadIdx.x) * 4;
    if (e >= TOTAL) return;
    int bc = (int)(e >> 12);
    float g = g_gate[bc];
    float4 xv = *(const float4*)&xin[e];
    float4 ev = *(const float4*)&g_enh[e];
    float4 o;
    o.x = xv.x + g * ev.x;
    o.y = xv.y + g * ev.y;
    o.z = xv.z + g * ev.z;
    o.w = xv.w + g * ev.w;
    *(float4*)&out[e] = o;
}

// ---------------- launch -------------------------------------------------------------
extern "C" void kernel_launch(void* const* d_in, const int* in_sizes, int n_in,
                              void* d_out, int out_size) {
    const float* x       = (const float*)d_in[0];
    const float* w_embed = (const float*)d_in[1];
    const float* b_embed = (const float*)d_in[2];
    const float* bn1_g   = (const float*)d_in[3];
    const float* bn1_b   = (const float*)d_in[4];
    const float* bn1_m   = (const float*)d_in[5];
    const float* bn1_v   = (const float*)d_in[6];
    const float* w_enh   = (const float*)d_in[7];
    const float* b_enh   = (const float*)d_in[8];
    const float* bn2_g   = (const float*)d_in[9];
    const float* bn2_b   = (const float*)d_in[10];
    const float* bn2_m   = (const float*)d_in[11];
    const float* bn2_v   = (const float*)d_in[12];
    const float* w_g1    = (const float*)d_in[13];
    const float* b_g1    = (const float*)d_in[14];
    const float* w_g2    = (const float*)d_in[15];
    const float* b_g2    = (const float*)d_in[16];
    float* out = (float*)d_out;

    static bool attr_done = false;
    if (!attr_done) {
        cudaFuncSetAttribute(mma_gemm<256, 0>, cudaFuncAttributeMaxDynamicSharedMemorySize, GSMEM);
        cudaFuncSetAttribute(mma_gemm<512, 1>, cudaFuncAttributeMaxDynamicSharedMemorySize, GSMEM);
        attr_done = true;
    }

    fold_kernel<<<512, 256>>>(w_embed, b_embed, bn1_g, bn1_b, bn1_m, bn1_v,
                              w_enh,   b_enh,   bn2_g, bn2_b, bn2_m, bn2_v);

    mma_gemm<256, 0><<<dim3(32, Bq), 256, GSMEM>>>(x);          // fe + norm
    simdot_kernel<<<dim3(16, 8, Bq), 256>>>();                  // 3rd
    simsoft_kernel<<<(Bq * HWc) / 256, 256>>>();
    agg_kernel<<<dim3(16, Cc / CKC, Bq), 256>>>(x);             // + fused pool-of-x
    mma_gemm<512, 1><<<dim3(32, Bq), 256, GSMEM>>>(x);          // enhanced + pool partials

    gate_kernel<<<Bq, 256>>>(w_g1, b_g1, w_g2, b_g2);
    final_kernel<<<(unsigned)(TOTAL / 4 / 256), 256>>>(x, out);
}

// round 16
// speedup vs baseline: 1.2576x; 1.0088x over previous
#include <cuda_runtime.h>
#include <cstdint>
#include <cstddef>

#define Bq   8
#define Cc   256
#define Hh   64
#define Ww   64
#define HWc  4096
#define TOTAL (8UL*256*4096)

// ---------------- scratch (device globals) ------------------------------------
__device__ float g_fe  [TOTAL];
__device__ float g_agg [TOTAL];
__device__ float g_enh [TOTAL];
__device__ float g_w1p [256*256];
__device__ float g_w2p [256*512];
__device__ float g_b1f [256];
__device__ float g_b2f [256];
__device__ float g_nrm [Bq*HWc];
__device__ float g_dotp[8*Bq*HWc*4];   // partial dots [split][b][hw][4 dirs] (float4)
__device__ float g_simw[Bq*9*HWc];
__device__ float g_poolp[Bq*32*256];
__device__ float g_pxp [Bq*16*256];
__device__ float g_gate[Bq*256];

// ---------------- BN fold (both weights in one launch) --------------------------
__global__ void fold_kernel(const float* __restrict__ w1, const float* __restrict__ b1s,
                            const float* __restrict__ g1, const float* __restrict__ t1,
                            const float* __restrict__ m1, const float* __restrict__ v1,
                            const float* __restrict__ w2, const float* __restrict__ b2s,
                            const float* __restrict__ g2, const float* __restrict__ t2,
                            const float* __restrict__ m2, const float* __restrict__ v2) {
    const int which = blockIdx.x >> 8;
    const int o = blockIdx.x & 255;
    const int cin = which ? 512 : 256;
    const float* w   = which ? w2  : w1;
    const float* bs  = which ? b2s : b1s;
    const float* gm  = which ? g2  : g1;
    const float* bt  = which ? t2  : t1;
    const float* mn  = which ? m2  : m1;
    const float* vr  = which ? v2  : v1;
    float inv = gm[o] * rsqrtf(vr[o] + 1e-5f);
    float* wp = which ? g_w2p : g_w1p;
    float* bf = which ? g_b2f : g_b1f;
    const int tile = o >> 4;
    const int r = o & 15;
    const int gqv = r & 7;
    const int hi = r >> 3;
    for (int k = threadIdx.x; k < cin; k += blockDim.x) {
        int ci = k >> 4, kk = k & 15;
        int k8 = kk >> 3, kw = kk & 7;
        int lane = gqv * 4 + (kw & 3);
        int e = hi + ((kw >> 2) << 1);
        wp[(size_t)ci * 4096 + tile * 256 + k8 * 128 + lane * 4 + e] = inv * w[o * cin + k];
    }
    if (threadIdx.x == 0)
        bf[o] = bs[o] * inv + bt[o] - mn[o] * inv;
}

// ---------------- mma.sync tf32 GEMM (unchanged) --------------------------------
#define BK   16
#define PADB 136
#define NSTG 4
#define ABUF 4096
#define BBUF (BK * PADB)
#define GSMEM (NSTG * (ABUF + BBUF) * 4)

__device__ __forceinline__ void mma_tf32(float c[4], const uint32_t a[4], const uint32_t b[2]) {
    asm volatile(
        "mma.sync.aligned.m16n8k8.row.col.f32.tf32.tf32.f32 "
        "{%0,%1,%2,%3}, {%4,%5,%6,%7}, {%8,%9}, {%0,%1,%2,%3};"
        : "+f"(c[0]), "+f"(c[1]), "+f"(c[2]), "+f"(c[3])
        : "r"(a[0]), "r"(a[1]), "r"(a[2]), "r"(a[3]), "r"(b[0]), "r"(b[1]));
}

template <int CIN, int PHASE>
__global__ __launch_bounds__(256) void mma_gemm(const float* __restrict__ xin) {
    extern __shared__ float dsm[];
    float* sA = dsm;
    float* sB = dsm + NSTG * ABUF;
    float* sred = sB;

    const int tid  = threadIdx.x;
    const int wid  = tid >> 5;
    const int lane = tid & 31;
    const int wm = wid >> 1;
    const int wn = wid & 1;
    const int gq = lane >> 2;
    const int tg = lane & 3;

    const int bb = blockIdx.y;
    const int n0 = blockIdx.x * 128;

    const float* Ap   = PHASE ? g_w2p : g_w1p;
    const float* bias = PHASE ? g_b2f : g_b1f;
    float*       out  = PHASE ? g_enh : g_fe;
    const float* xb   = xin   + (size_t)bb * Cc * HWc;
    const float* aggb = g_agg + (size_t)bb * Cc * HWc;

    uint32_t sAa, sBa;
    asm("{ .reg .u64 t; cvta.to.shared.u64 t, %1; cvt.u32.u64 %0, t; }" : "=r"(sAa) : "l"(sA));
    asm("{ .reg .u64 t; cvta.to.shared.u64 t, %1; cvt.u32.u64 %0, t; }" : "=r"(sBa) : "l"(sB));

    auto fill = [&](int ci) {
        const int buf = ci & (NSTG - 1);
        const int k0 = ci * BK;
        const uint32_t sAb = sAa + buf * (ABUF * 4);
        const uint32_t sBb = sBa + buf * (BBUF * 4);
#pragma unroll
        for (int it = 0; it < 4; it++) {
            int id = it * 256 + tid;
            const float* gp = &Ap[(size_t)ci * 4096 + id * 4];
            asm volatile("cp.async.cg.shared.global [%0], [%1], 16;"
                         :: "r"(sAb + (uint32_t)id * 16), "l"(gp));
        }
#pragma unroll
        for (int it = 0; it < 2; it++) {
            int id = it * 256 + tid;
            int kr = id >> 5, q = id & 31;
            int kg = k0 + kr;
            const float* brow;
            if (PHASE == 0) brow = xb + (size_t)kg * HWc;
            else            brow = (kg < Cc) ? xb + (size_t)kg * HWc
                                             : aggb + (size_t)(kg - Cc) * HWc;
            const float* gp = &brow[n0 + q * 4];
            uint32_t s = sBb + (uint32_t)(kr * PADB + q * 4) * 4;
            asm volatile("cp.async.cg.shared.global [%0], [%1], 16;" :: "r"(s), "l"(gp));
        }
        asm volatile("cp.async.commit_group;" ::: "memory");
    };

    float acc[4][8][4];
#pragma unroll
    for (int mt = 0; mt < 4; mt++)
#pragma unroll
        for (int nt = 0; nt < 8; nt++)
#pragma unroll
            for (int i = 0; i < 4; i++) acc[mt][nt][i] = 0.f;

    constexpr int NC = CIN / BK;
    fill(0); fill(1); fill(2);

    for (int ci = 0; ci < NC; ci++) {
        const int rem = NC - 1 - ci;
        if (rem >= 2)      asm volatile("cp.async.wait_group 2;" ::: "memory");
        else if (rem == 1) asm volatile("cp.async.wait_group 1;" ::: "memory");
        else               asm volatile("cp.async.wait_group 0;" ::: "memory");
        __syncthreads();
        if (ci + 3 < NC) fill(ci + 3);

        const int buf = ci & (NSTG - 1);
        const float* A_ = sA + buf * ABUF;
        const float* B_ = sB + buf * BBUF;
#pragma unroll
        for (int k8 = 0; k8 < 2; k8++) {
            const int kb = k8 * 8;
            uint32_t afr[4][4];
#pragma unroll
            for (int mt = 0; mt < 4; mt++) {
                int tile = wm * 4 + mt;
                const float4 v = *(const float4*)&A_[(tile * 2 + k8) * 128 + lane * 4];
                afr[mt][0] = __float_as_uint(v.x);
                afr[mt][1] = __float_as_uint(v.y);
                afr[mt][2] = __float_as_uint(v.z);
                afr[mt][3] = __float_as_uint(v.w);
            }
            uint32_t bfr[8][2];
#pragma unroll
            for (int nt = 0; nt < 8; nt++) {
                int col = wn * 64 + nt * 8 + gq;
                bfr[nt][0] = __float_as_uint(B_[(kb + tg) * PADB + col]);
                bfr[nt][1] = __float_as_uint(B_[(kb + 4 + tg) * PADB + col]);
            }
#pragma unroll
            for (int mt = 0; mt < 4; mt++)
#pragma unroll
                for (int nt = 0; nt < 8; nt++)
                    mma_tf32(acc[mt][nt], afr[mt], bfr[nt]);
        }
    }
    __syncthreads();

    float ssq[8][2];
    float prt[4][2];
    if (PHASE == 0) {
#pragma unroll
        for (int nt = 0; nt < 8; nt++) { ssq[nt][0] = 0.f; ssq[nt][1] = 0.f; }
    } else {
#pragma unroll
        for (int mt = 0; mt < 4; mt++) { prt[mt][0] = 0.f; prt[mt][1] = 0.f; }
    }

#pragma unroll
    for (int mt = 0; mt < 4; mt++) {
        int row0 = wm * 64 + mt * 16 + gq;
        float bs0 = bias[row0];
        float bs1 = bias[row0 + 8];
        float* o0 = out + ((size_t)bb * Cc + row0) * HWc + n0;
        float* o1 = o0 + 8 * HWc;
#pragma unroll
        for (int nt = 0; nt < 8; nt++) {
            int col = wn * 64 + nt * 8 + 2 * tg;
            float v0x = fmaxf(acc[mt][nt][0] + bs0, 0.f);
            float v0y = fmaxf(acc[mt][nt][1] + bs0, 0.f);
            float v1x = fmaxf(acc[mt][nt][2] + bs1, 0.f);
            float v1y = fmaxf(acc[mt][nt][3] + bs1, 0.f);
            float2 a = {v0x, v0y}, b2 = {v1x, v1y};
            *(float2*)&o0[col] = a;
            *(float2*)&o1[col] = b2;
            if (PHASE == 0) {
                ssq[nt][0] += v0x * v0x + v1x * v1x;
                ssq[nt][1] += v0y * v0y + v1y * v1y;
            } else {
                prt[mt][0] += v0x + v0y;
                prt[mt][1] += v1x + v1y;
            }
        }
    }

    if (PHASE == 0) {
#pragma unroll
        for (int nt = 0; nt < 8; nt++) {
#pragma unroll
            for (int off = 16; off >= 4; off >>= 1) {
                ssq[nt][0] += __shfl_down_sync(0xffffffffu, ssq[nt][0], off);
                ssq[nt][1] += __shfl_down_sync(0xffffffffu, ssq[nt][1], off);
            }
        }
        if (lane < 4) {
#pragma unroll
            for (int nt = 0; nt < 8; nt++) {
                int col = wn * 64 + nt * 8 + 2 * tg;
                sred[wm * 128 + col]     = ssq[nt][0];
                sred[wm * 128 + col + 1] = ssq[nt][1];
            }
        }
        __syncthreads();
        if (tid < 128) {
            float s = sred[tid] + sred[128 + tid] + sred[256 + tid] + sred[384 + tid];
            g_nrm[bb * HWc + n0 + tid] = sqrtf(s);
        }
    } else {
#pragma unroll
        for (int mt = 0; mt < 4; mt++) {
            prt[mt][0] += __shfl_down_sync(0xffffffffu, prt[mt][0], 2);
            prt[mt][0] += __shfl_down_sync(0xffffffffu, prt[mt][0], 1);
            prt[mt][1] += __shfl_down_sync(0xffffffffu, prt[mt][1], 2);
            prt[mt][1] += __shfl_down_sync(0xffffffffu, prt[mt][1], 1);
        }
        if (tg == 0) {
#pragma unroll
            for (int mt = 0; mt < 4; mt++) {
                int row0 = wm * 64 + mt * 16 + gq;
                sred[wn * 256 + row0]     = prt[mt][0];
                sred[wn * 256 + row0 + 8] = prt[mt][1];
            }
        }
        __syncthreads();
        if (tid < 256)
            g_poolp[((size_t)bb * 32 + blockIdx.x) * 256 + tid] =
                sred[tid] + sred[256 + tid];
    }
}

// ---------------- phase A: 4-dir partial dots (float4 store) ---------------------
#define TILE 16
#define HALO 18
#define NPIX (HALO * HALO)
#define SDSTR 36
__global__ __launch_bounds__(256) void simdot_kernel() {
    __shared__ float sh[NPIX * SDSTR];

    const int b  = blockIdx.z;
    const int sp = blockIdx.y;
    const int t  = blockIdx.x;
    const int h0 = (t >> 2) * TILE;
    const int w0 = (t & 3) * TILE;
    const int lx = threadIdx.x & (TILE - 1);
    const int ly = threadIdx.x / TILE;
    const int pc = ly * HALO + lx;

    const float* feb = g_fe + (size_t)b * Cc * HWc + (size_t)(sp * 32) * HWc;

    {
        int hy = threadIdx.x / HALO;
        int hx = threadIdx.x - hy * HALO;
        int c = 0;
        for (int idx = threadIdx.x; idx < 32 * NPIX; idx += 256) {
            int gh = h0 + hy - 1, gw = w0 + hx - 1;
            float v = 0.f;
            if (gh >= 0 && gh < Hh && gw >= 0 && gw < Ww)
                v = feb[(size_t)c * HWc + gh * Ww + gw];
            sh[(hy * HALO + hx) * SDSTR + c] = v;
            hy += 14; hx += 4;
            if (hx >= HALO) { hx -= HALO; hy++; }
            if (hy >= HALO) { hy -= HALO; c++; }
        }
    }
    __syncthreads();

    float4 dot4[4];
#pragma unroll
    for (int k = 0; k < 4; k++) dot4[k] = make_float4(0.f, 0.f, 0.f, 0.f);

#pragma unroll
    for (int c4 = 0; c4 < 8; c4++) {
        float4 ctr = *(const float4*)&sh[(pc + HALO + 1) * SDSTR + c4 * 4];
        const int nbo[4] = { pc, pc + 1, pc + 2, pc + HALO };
#pragma unroll
        for (int k = 0; k < 4; k++) {
            float4 nb = *(const float4*)&sh[nbo[k] * SDSTR + c4 * 4];
            dot4[k].x += ctr.x * nb.x;
            dot4[k].y += ctr.y * nb.y;
            dot4[k].z += ctr.z * nb.z;
            dot4[k].w += ctr.w * nb.w;
        }
    }

    const int hw = (h0 + ly) * Ww + w0 + lx;
    float4 o;
    o.x = dot4[0].x + dot4[0].y + dot4[0].z + dot4[0].w;
    o.y = dot4[1].x + dot4[1].y + dot4[1].z + dot4[1].w;
    o.z = dot4[2].x + dot4[2].y + dot4[2].z + dot4[2].w;
    o.w = dot4[3].x + dot4[3].y + dot4[3].z + dot4[3].w;
    *(float4*)&g_dotp[(((size_t)sp * Bq + b) * HWc + hw) * 4] = o;
}

// ---------------- phase B: reconstruct 9 sims, cosine + softmax ------------------
__global__ __launch_bounds__(128) void simsoft_kernel() {
    const int idx = blockIdx.x * 128 + threadIdx.x;
    const int b = idx >> 12;
    const int hw = idx & 4095;
    const int h = hw >> 6, w = hw & 63;

    float nc = g_nrm[b * HWc + hw];
    float s[9];

    // direct dirs: one float4 per split (8 independent 16B loads)
    float4 dsum = make_float4(0.f, 0.f, 0.f, 0.f);
#pragma unroll
    for (int sp = 0; sp < 8; sp++) {
        float4 v = *(const float4*)&g_dotp[(((size_t)sp * Bq + b) * HWc + hw) * 4];
        dsum.x += v.x; dsum.y += v.y; dsum.z += v.z; dsum.w += v.w;
    }
    const int dh0[4] = {-1, -1, -1, 0};
    const int dw0[4] = {-1,  0,  1, -1};
    const float dd[4] = {dsum.x, dsum.y, dsum.z, dsum.w};
#pragma unroll
    for (int k = 0; k < 4; k++) {
        int nh = h + dh0[k], nw = w + dw0[k];
        float np = (nh >= 0 && nh < Hh && nw >= 0 && nw < Ww)
                       ? g_nrm[b * HWc + nh * Ww + nw] : 0.f;
        s[k] = dd[k] / (nc * np + 1e-7f);
    }
    s[4] = (nc * nc) / (nc * nc + 1e-7f);

    // mirrors: accumulate 4 independent chains (scalar loads, batched)
    float md[4];
    bool mv[4];
    int mq[4];
#pragma unroll
    for (int k = 5; k < 9; k++) {
        int m = 8 - k;
        int nh = h - dh0[m], nw = w - dw0[m];
        mv[k - 5] = (nh >= 0 && nh < Hh && nw >= 0 && nw < Ww);
        mq[k - 5] = mv[k - 5] ? nh * Ww + nw : 0;
        md[k - 5] = 0.f;
    }
#pragma unroll
    for (int sp = 0; sp < 8; sp++) {
        const float* base = &g_dotp[(((size_t)sp * Bq + b) * HWc) * 4];
#pragma unroll
        for (int j = 0; j < 4; j++)
            md[j] += base[(size_t)mq[j] * 4 + (3 - j)];
    }
#pragma unroll
    for (int k = 5; k < 9; k++) {
        int j = k - 5;
        if (mv[j]) {
            float np = g_nrm[b * HWc + mq[j]];
            s[k] = md[j] / (nc * np + 1e-7f);
        } else {
            s[k] = 0.f;
        }
    }

    float mx = s[0];
#pragma unroll
    for (int k = 1; k < 9; k++) mx = fmaxf(mx, s[k]);
    float sum = 0.f;
#pragma unroll
    for (int k = 0; k < 9; k++) { s[k] = expf(s[k] - mx); sum += s[k]; }
    float inv = 1.f / sum;
#pragma unroll
    for (int k = 0; k < 9; k++)
        g_simw[((size_t)b * 9 + k) * HWc + hw] = s[k] * inv;
}

// ---------------- phase C: 3x3 aggregation + fused pool-of-x ---------------------
#define CKC  16
#define SHSTR 20
__global__ __launch_bounds__(256) void agg_kernel(const float* __restrict__ xin) {
    __shared__ float sh[NPIX * SHSTR];
    __shared__ float pred[256];

    const int b  = blockIdx.z;
    const int cc = blockIdx.y * CKC;
    const int t  = blockIdx.x;
    const int h0 = (t >> 2) * TILE;
    const int w0 = (t & 3) * TILE;
    const int lx = threadIdx.x & (TILE - 1);
    const int ly = threadIdx.x / TILE;
    const int pc = ly * HALO + lx;
    const int tid = threadIdx.x;

    const float* xb = xin + (size_t)b * Cc * HWc + (size_t)cc * HWc;

    {
        int hy = tid / HALO;
        int hx = tid - hy * HALO;
        int c = 0;
        for (int idx = tid; idx < CKC * NPIX; idx += 256) {
            int gh = h0 + hy - 1, gw = w0 + hx - 1;
            float v = 0.f;
            if (gh >= 0 && gh < Hh && gw >= 0 && gw < Ww)
                v = xb[(size_t)c * HWc + gh * Ww + gw];
            sh[(hy * HALO + hx) * SHSTR + c] = v;
            hy += 14; hx += 4;
            if (hx >= HALO) { hx -= HALO; hy++; }
            if (hy >= HALO) { hy -= HALO; c++; }
        }
    }
    __syncthreads();

    const int hw = (h0 + ly) * Ww + w0 + lx;
    float s[9];
#pragma unroll
    for (int k = 0; k < 9; k++)
        s[k] = g_simw[((size_t)b * 9 + k) * HWc + hw];

    float* aggb = g_agg + (size_t)b * Cc * HWc;
#pragma unroll
    for (int c4 = 0; c4 < 4; c4++) {
        float4 a = make_float4(0.f, 0.f, 0.f, 0.f);
#pragma unroll
        for (int di = 0; di < 3; di++)
#pragma unroll
            for (int dj = 0; dj < 3; dj++) {
                float4 nb = *(const float4*)&sh[(pc + di * HALO + dj) * SHSTR + c4 * 4];
                float wk = s[di * 3 + dj];
                a.x += wk * nb.x;
                a.y += wk * nb.y;
                a.z += wk * nb.z;
                a.w += wk * nb.w;
            }
        size_t base = (size_t)(cc + c4 * 4) * HWc + hw;
        aggb[base]           = a.x;
        aggb[base + HWc]     = a.y;
        aggb[base + 2 * HWc] = a.z;
        aggb[base + 3 * HWc] = a.w;
    }

    {
        const int cl = tid & 15;
        const int pg = tid >> 4;
        float sum = 0.f;
#pragma unroll
        for (int i = 0; i < 16; i++)
            sum += sh[((pg + 1) * HALO + i + 1) * SHSTR + cl];
        pred[pg * 16 + cl] = sum;
    }
    __syncthreads();
    if (tid < 16) {
        float sum = 0.f;
#pragma unroll
        for (int g = 0; g < 16; g++) sum += pred[g * 16 + tid];
        g_pxp[((size_t)b * 16 + t) * 256 + cc + tid] = sum;
    }
}

// ---------------- SE gate ---------------------------------------------------------
__global__ void gate_kernel(const float* __restrict__ w1, const float* __restrict__ b1,
                            const float* __restrict__ w2, const float* __restrict__ b2) {
    const int b = blockIdx.x;
    const int tid = threadIdx.x;
    __shared__ float sp[512];
    __shared__ float shid[64];
    float sx = 0.f;
#pragma unroll
    for (int t = 0; t < 16; t++)
        sx += g_pxp[((size_t)b * 16 + t) * 256 + tid];
    sp[tid] = sx * (1.f / HWc);
    float s0 = 0.f;
#pragma unroll 8
    for (int nb = 0; nb < 32; nb++)
        s0 += g_poolp[((size_t)b * 32 + nb) * 256 + tid];
    sp[256 + tid] = s0 * (1.f / HWc);
    __syncthreads();
    if (tid < 64) {
        float s = b1[tid];
        const float* wr = w1 + tid * 512;
#pragma unroll 8
        for (int c = 0; c < 512; c++) s += wr[c] * sp[c];
        shid[tid] = fmaxf(s, 0.f);
    }
    __syncthreads();
    float s = b2[tid];
    const float* wr = w2 + tid * 64;
#pragma unroll
    for (int j = 0; j < 64; j++) s += wr[j] * shid[j];
    g_gate[b * 256 + tid] = 1.f / (1.f + expf(-s));
}

// ---------------- residual + gated enhancement -------------------------------------
__global__ void final_kernel(const float* __restrict__ xin, float* __restrict__ out) {
    size_t e = ((size_t)blockIdx.x * blockDim.x + threadIdx.x) * 4;
    if (e >= TOTAL) return;
    int bc = (int)(e >> 12);
    float g = g_gate[bc];
    float4 xv = *(const float4*)&xin[e];
    float4 ev = *(const float4*)&g_enh[e];
    float4 o;
    o.x = xv.x + g * ev.x;
    o.y = xv.y + g * ev.y;
    o.z = xv.z + g * ev.z;
    o.w = xv.w + g * ev.w;
    *(float4*)&out[e] = o;
}

// ---------------- launch -------------------------------------------------------------
extern "C" void kernel_launch(void* const* d_in, const int* in_sizes, int n_in,
                              void* d_out, int out_size) {
    const float* x       = (const float*)d_in[0];
    const float* w_embed = (const float*)d_in[1];
    const float* b_embed = (const float*)d_in[2];
    const float* bn1_g   = (const float*)d_in[3];
    const float* bn1_b   = (const float*)d_in[4];
    const float* bn1_m   = (const float*)d_in[5];
    const float* bn1_v   = (const float*)d_in[6];
    const float* w_enh   = (const float*)d_in[7];
    const float* b_enh   = (const float*)d_in[8];
    const float* bn2_g   = (const float*)d_in[9];
    const float* bn2_b   = (const float*)d_in[10];
    const float* bn2_m   = (const float*)d_in[11];
    const float* bn2_v   = (const float*)d_in[12];
    const float* w_g1    = (const float*)d_in[13];
    const float* b_g1    = (const float*)d_in[14];
    const float* w_g2    = (const float*)d_in[15];
    const float* b_g2    = (const float*)d_in[16];
    float* out = (float*)d_out;

    static bool attr_done = false;
    if (!attr_done) {
        cudaFuncSetAttribute(mma_gemm<256, 0>, cudaFuncAttributeMaxDynamicSharedMemorySize, GSMEM);
        cudaFuncSetAttribute(mma_gemm<512, 1>, cudaFuncAttributeMaxDynamicSharedMemorySize, GSMEM);
        attr_done = true;
    }

    fold_kernel<<<512, 256>>>(w_embed, b_embed, bn1_g, bn1_b, bn1_m, bn1_v,
                              w_enh,   b_enh,   bn2_g, bn2_b, bn2_m, bn2_v);

    mma_gemm<256, 0><<<dim3(32, Bq), 256, GSMEM>>>(x);          // fe + norm
    simdot_kernel<<<dim3(16, 8, Bq), 256>>>();
    simsoft_kernel<<<(Bq * HWc) / 128, 128>>>();                // 4th: profiled
    agg_kernel<<<dim3(16, Cc / CKC, Bq), 256>>>(x);
    mma_gemm<512, 1><<<dim3(32, Bq), 256, GSMEM>>>(x);          // enhanced + pool partials

    gate_kernel<<<Bq, 256>>>(w_g1, b_g1, w_g2, b_g2);
    final_kernel<<<(unsigned)(TOTAL / 4 / 256), 256>>>(x, out);
}